// round 3
// baseline (speedup 1.0000x reference)
#include <cuda_runtime.h>
#include <cstddef>

#define NTOT 4096
#define HD   256
#define LEN  32
#define KOBS 32
#define VOBS 128
#define VC   32
#define NL   131072   // NTOT*LEN

typedef unsigned long long ull;

// ---------------- scratch (static device memory; no allocation) ----------------
__device__ float g_Mobs[KOBS * VOBS * HD];       // [k][v][h]   4 MB
__device__ float g_Q[16 * VC * 64];              // [tap][v][o] 128 KB
__device__ int   g_tok[NL];                      // argmax tokens
__device__ float g_ypre[(size_t)NL * HD];        // pre-BN conv output [n][l][h] 134 MB
__device__ float g_bnsum[HD];
__device__ float g_bnsq[HD];
__device__ float g_bnscale[HD];
__device__ float g_bnshift[HD];
__device__ float g_xp[(size_t)LEN * 3 * NTOT * HD]; // [l][g][n][h] 402 MB
__device__ float g_hout[(size_t)NTOT * HD];      // final GRU hidden

__device__ __forceinline__ float prelu_f(float x, float a) { return x >= 0.f ? x : a * x; }

// packed fp32x2 FMA (Blackwell FFMA2 — 2 MACs / instruction)
__device__ __forceinline__ ull ffma2(ull a, ull b, ull c) {
    ull d;
    asm("fma.rn.f32x2 %0, %1, %2, %3;" : "=l"(d) : "l"(a), "l"(b), "l"(c));
    return d;
}
__device__ __forceinline__ ull pack2dup(float x) {
    ull d;
    asm("mov.b64 %0, {%1, %2};" : "=l"(d) : "f"(x), "f"(x));
    return d;
}
__device__ __forceinline__ float2 unpack2(ull v) {
    float2 r;
    asm("mov.b64 {%0, %1}, %2;" : "=f"(r.x), "=f"(r.y) : "l"(v));
    return r;
}
__device__ __forceinline__ float sigmoidf_(float x) { return 1.f / (1.f + __expf(-x)); }

// ---------------- zero init (BN accumulators; re-zeroed every replay) ----------------
__global__ void k_zero() {
    int i = threadIdx.x;
    if (i < HD) { g_bnsum[i] = 0.f; g_bnsq[i] = 0.f; }
}

// ---------------- obs lookup table: M[k][v][h] = prelu(obs_emb[v]) @ obs_W[k*H:(k+1)*H, :] ----------------
__global__ void k_obsM(const float* __restrict__ obs_emb, const float* __restrict__ aemb_p,
                       const float* __restrict__ obs_W) {
    __shared__ float P[8 * HD];
    int k = blockIdx.y;
    int vbase = blockIdx.x * 8;
    int tid = threadIdx.x;
    float a = *aemb_p;
    for (int t = tid; t < 8 * HD; t += 256)
        P[t] = prelu_f(obs_emb[vbase * HD + t], a);
    __syncthreads();

    float acc[8];
#pragma unroll
    for (int v = 0; v < 8; v++) acc[v] = 0.f;
    const float* Wp = obs_W + (size_t)k * HD * HD + tid;
    for (int i = 0; i < HD; i++) {
        float w = Wp[(size_t)i * HD];
#pragma unroll
        for (int v = 0; v < 8; v++) acc[v] += P[v * HD + i] * w;
    }
#pragma unroll
    for (int v = 0; v < 8; v++)
        g_Mobs[((size_t)k * VOBS + vbase + v) * HD + tid] = acc[v];
}

// ---------------- conv lookup tables: Q[tap][v][o] ----------------
__global__ void k_Q(const float* __restrict__ ce, const float* __restrict__ cap,
                    const float* __restrict__ cw1, const float* __restrict__ cw3,
                    const float* __restrict__ cw5, const float* __restrict__ cw7) {
    __shared__ float Pc[HD * VC];
    int tap = blockIdx.x, tid = threadIdx.x;
    float a = *cap;
    for (int t = tid; t < VC * HD; t += 256) {
        int v = t >> 8, i = t & 255;
        Pc[i * VC + v] = prelu_f(ce[t], a);
    }
    __syncthreads();

    int g, tt;
    if (tap == 0)       { g = 0; tt = 0; }
    else if (tap < 4)   { g = 1; tt = tap - 1; }
    else if (tap < 9)   { g = 2; tt = tap - 4; }
    else                { g = 3; tt = tap - 9; }
    int ks = 2 * g + 1;
    const float* w = (g == 0) ? cw1 : (g == 1) ? cw3 : (g == 2) ? cw5 : cw7;

    int idx = blockIdx.y * 256 + tid;
    int o = idx >> 5, v = idx & 31;
    float acc = 0.f;
    for (int i = 0; i < HD; i++)
        acc += Pc[i * VC + v] * w[((size_t)o * HD + i) * ks + tt];
    g_Q[(tap * VC + v) * 64 + o] = acc;
}

// ---------------- token argmax (first-index tie break) ----------------
__global__ void k_tok(const float* __restrict__ comm) {
    int warp = (blockIdx.x * blockDim.x + threadIdx.x) >> 5;
    int lane = threadIdx.x & 31;
    if (warp >= NL) return;
    float v = comm[(size_t)warp * VC + lane];
    int idx = lane;
#pragma unroll
    for (int off = 16; off; off >>= 1) {
        float ov = __shfl_xor_sync(0xffffffffu, v, off);
        int   oi = __shfl_xor_sync(0xffffffffu, idx, off);
        if (ov > v || (ov == v && oi < idx)) { v = ov; idx = oi; }
    }
    if (lane == 0) g_tok[warp] = idx;
}

// ---------------- obs output half ----------------
__global__ void k_obsOut(const float* __restrict__ obs, const float* __restrict__ obs_b,
                         const float* __restrict__ obs_a_p, float* __restrict__ out) {
    __shared__ int sidx[KOBS];
    __shared__ int wcnt[8];
    int n = blockIdx.x, tid = threadIdx.x;
    int flag = 0;
    if (tid < VOBS) flag = obs[(size_t)n * VOBS + tid] > 0.5f;
    unsigned mask = __ballot_sync(0xffffffffu, flag);
    int lane = tid & 31, w = tid >> 5;
    if (lane == 0) wcnt[w] = __popc(mask);
    __syncthreads();
    if (flag) {
        int base = 0;
        for (int j = 0; j < w; j++) base += wcnt[j];
        sidx[base + __popc(mask & ((1u << lane) - 1u))] = tid;
    }
    __syncthreads();

    float acc = obs_b[tid];
#pragma unroll 8
    for (int k = 0; k < KOBS; k++)
        acc += g_Mobs[((size_t)k * VOBS + sidx[k]) * HD + tid];
    out[(size_t)n * (2 * HD) + tid] = prelu_f(acc, *obs_a_p);
}

// ---------------- conv-as-lookup -> y_pre + BN partial sums ----------------
__global__ void k_ypre(const float* __restrict__ cb1, const float* __restrict__ cb3,
                       const float* __restrict__ cb5, const float* __restrict__ cb7) {
    __shared__ int tk[LEN];
    int n = blockIdx.x, tid = threadIdx.x;
    if (tid < LEN) tk[tid] = g_tok[n * LEN + tid];
    __syncthreads();

    int g = tid >> 6, o = tid & 63;
    int ks = 2 * g + 1, pad = g, base = g * g;
    const float* cbp = (g == 0) ? cb1 : (g == 1) ? cb3 : (g == 2) ? cb5 : cb7;
    float bias = cbp[o];

    float ls = 0.f, lq = 0.f;
    for (int l = 0; l < LEN; l++) {
        float acc = bias;
        for (int t = 0; t < ks; t++) {
            int lp = l + t - pad;
            if (lp >= 0 && lp < LEN)
                acc += g_Q[((base + t) * VC + tk[lp]) * 64 + o];
        }
        g_ypre[((size_t)n * LEN + l) * HD + tid] = acc;
        ls += acc; lq += acc * acc;
    }
    atomicAdd(&g_bnsum[tid], ls);
    atomicAdd(&g_bnsq[tid], lq);
}

// ---------------- BN finalize ----------------
__global__ void k_bnfin(const float* __restrict__ bn_g, const float* __restrict__ bn_b) {
    int h = threadIdx.x;
    float m   = g_bnsum[h] * (1.0f / 131072.0f);
    float var = g_bnsq[h]  * (1.0f / 131072.0f) - m * m;
    float sc  = bn_g[h] * rsqrtf(var + 1e-5f);
    g_bnscale[h] = sc;
    g_bnshift[h] = bn_b[h] - m * sc;
}

// ---------------- xproj GEMM (FFMA2): A=[131072,256] x Wx -> g_xp ----------------
// tile M=128, N=128 (within one gate since 128 | 256), block 256 thr, 8 rows x 8 cols / thr
__global__ void __launch_bounds__(256) k_xproj(const float* __restrict__ Wx,
                                               const float* __restrict__ bx,
                                               const float* __restrict__ cnn_a_p) {
    __shared__ __align__(16) float As[128][33];
    __shared__ __align__(16) float Bs[32][132];
    float ca = *cnn_a_p;
    int tid = threadIdx.x;
    int rowbase = blockIdx.x * 128;
    int cb = blockIdx.y * 128;          // global col base (0..640)
    int gsel = cb >> 8;                 // gate (const per block)
    int kb = cb & 255;                  // col-within-gate base
    int tx = tid & 15, ty = tid >> 4;

    ull acc[8][4];
#pragma unroll
    for (int j = 0; j < 8; j++)
#pragma unroll
        for (int u = 0; u < 4; u++) acc[j][u] = 0ull;

    for (int i0 = 0; i0 < HD; i0 += 32) {
        for (int t = tid; t < 128 * 32; t += 256) {
            int kk = t & 31, r = t >> 5;
            int ch = i0 + kk;
            float v = g_ypre[(size_t)(rowbase + r) * HD + ch];
            As[r][kk] = prelu_f(v * g_bnscale[ch] + g_bnshift[ch], ca);
        }
        for (int t = tid; t < 32 * 128; t += 256) {
            int c = t & 127, kk = t >> 7;
            Bs[kk][c] = Wx[((size_t)gsel * HD + i0 + kk) * HD + kb + c];
        }
        __syncthreads();
#pragma unroll
        for (int kk = 0; kk < 32; kk++) {
            ull a2[8];
#pragma unroll
            for (int j = 0; j < 8; j++) a2[j] = pack2dup(As[ty * 8 + j][kk]);
            ulonglong2 b0 = *(const ulonglong2*)&Bs[kk][tx * 8];
            ulonglong2 b1 = *(const ulonglong2*)&Bs[kk][tx * 8 + 4];
#pragma unroll
            for (int j = 0; j < 8; j++) {
                acc[j][0] = ffma2(a2[j], b0.x, acc[j][0]);
                acc[j][1] = ffma2(a2[j], b0.y, acc[j][1]);
                acc[j][2] = ffma2(a2[j], b1.x, acc[j][2]);
                acc[j][3] = ffma2(a2[j], b1.y, acc[j][3]);
            }
        }
        __syncthreads();
    }
#pragma unroll
    for (int j = 0; j < 8; j++) {
        int row = rowbase + ty * 8 + j;
        int n = row >> 5, l = row & 31;
#pragma unroll
        for (int u = 0; u < 4; u++) {
            float2 v = unpack2(acc[j][u]);
            int k0 = kb + tx * 8 + u * 2;
            float2 o;
            o.x = v.x + bx[gsel * HD + k0];
            o.y = v.y + bx[gsel * HD + k0 + 1];
            *(float2*)&g_xp[(((size_t)l * 3 + gsel) * NTOT + n) * HD + k0] = o;
        }
    }
}

// ---------------- persistent GRU: 128 CTAs x 32 rows, 32 steps, h in smem ----------------
#define HSTR 258
#define BSTR 776
__global__ void __launch_bounds__(256) k_gru_persist(const float* __restrict__ Wh,
                                                     const float* __restrict__ bh) {
    extern __shared__ float sm[];
    float* h_sh = sm;                         // [32][HSTR]
    float* Bsm  = sm + 32 * HSTR;             // [16][BSTR]

    int tid = threadIdx.x;
    int tx = tid & 31, w = tid >> 5;          // 8 warps
    int row0 = (w & 3) * 8;                   // 8 rows per thread
    int half = w >> 2;                        // hcol half (0/1)
    int base = blockIdx.x * 32;               // global row base

    // zero h
    for (int i = tid; i < 32 * HSTR; i += 256) h_sh[i] = 0.f;
    __syncthreads();

    // per-thread hcol pairs: hc = half*128 + p*64 + tx*2 + {0,1},  p in {0,1}
    float2 bhv[3][2];
#pragma unroll
    for (int g = 0; g < 3; g++)
#pragma unroll
        for (int p = 0; p < 2; p++)
            bhv[g][p] = *(const float2*)&bh[g * HD + half * 128 + p * 64 + tx * 2];

    for (int step = 0; step < LEN; step++) {
        ull acc[8][6];
#pragma unroll
        for (int r = 0; r < 8; r++)
#pragma unroll
            for (int u = 0; u < 6; u++) acc[r][u] = 0ull;

        for (int t0 = 0; t0 < HD; t0 += 16) {
            __syncthreads();   // Bs reuse / h-write ordering
            for (int i = tid; i < 16 * 768; i += 256) {
                int kk = i / 768, c = i - kk * 768;
                int g = c >> 8, hc = c & 255;
                Bsm[kk * BSTR + c] = Wh[((size_t)g * HD + t0 + kk) * HD + hc];
            }
            __syncthreads();
#pragma unroll
            for (int kk = 0; kk < 16; kk++) {
                ull a2[8];
#pragma unroll
                for (int r = 0; r < 8; r++)
                    a2[r] = pack2dup(h_sh[(row0 + r) * HSTR + t0 + kk]);
                const float* brow = &Bsm[kk * BSTR];
#pragma unroll
                for (int g = 0; g < 3; g++)
#pragma unroll
                    for (int p = 0; p < 2; p++) {
                        ull b = *(const ull*)&brow[g * 256 + half * 128 + p * 64 + tx * 2];
#pragma unroll
                        for (int r = 0; r < 8; r++)
                            acc[r][g * 2 + p] = ffma2(a2[r], b, acc[r][g * 2 + p]);
                    }
            }
        }
        __syncthreads();   // all h reads done before writes

        // gate math + h update
#pragma unroll
        for (int r = 0; r < 8; r++) {
            int row = row0 + r;
            int grow = base + row;
#pragma unroll
            for (int p = 0; p < 2; p++) {
                int hc = half * 128 + p * 64 + tx * 2;
                float2 pr = unpack2(acc[r][p]);
                float2 pz = unpack2(acc[r][2 + p]);
                float2 pn = unpack2(acc[r][4 + p]);
                size_t xb = (((size_t)step * 3) * NTOT + grow) * HD + hc;
                float2 xr = *(const float2*)&g_xp[xb];
                float2 xz = *(const float2*)&g_xp[xb + (size_t)NTOT * HD];
                float2 xn = *(const float2*)&g_xp[xb + 2 * (size_t)NTOT * HD];
                float2 ho = *(const float2*)&h_sh[row * HSTR + hc];
                float rr0 = sigmoidf_(xr.x + pr.x + bhv[0][p].x);
                float rr1 = sigmoidf_(xr.y + pr.y + bhv[0][p].y);
                float zz0 = sigmoidf_(xz.x + pz.x + bhv[1][p].x);
                float zz1 = sigmoidf_(xz.y + pz.y + bhv[1][p].y);
                float nn0 = tanhf(xn.x + rr0 * (pn.x + bhv[2][p].x));
                float nn1 = tanhf(xn.y + rr1 * (pn.y + bhv[2][p].y));
                float2 hn;
                hn.x = nn0 * (1.f - zz0) + ho.x * zz0;
                hn.y = nn1 * (1.f - zz1) + ho.y * zz1;
                *(float2*)&h_sh[row * HSTR + hc] = hn;
            }
        }
        // next iteration's first __syncthreads orders write->read
    }
    __syncthreads();
    // write out final h
    for (int i = tid; i < 32 * HD; i += 256) {
        int r = i >> 8, c = i & 255;
        g_hout[(size_t)(base + r) * HD + c] = h_sh[r * HSTR + c];
    }
}

// ---------------- final linear: prelu(prelu(h)@W + b) -> out[:,256:512] ----------------
__global__ void k_final(const float* __restrict__ linW, const float* __restrict__ linb,
                        const float* __restrict__ a1p, const float* __restrict__ a2p,
                        float* __restrict__ out) {
    __shared__ __align__(16) float As[64][33];
    __shared__ __align__(16) float Bs[32][64];
    float a1 = *a1p, a2 = *a2p;
    int tid = threadIdx.x;
    int rowbase = blockIdx.x * 64, cbase = blockIdx.y * 64;
    int tx = tid & 15, ty = tid >> 4;

    float acc[4][4];
#pragma unroll
    for (int j = 0; j < 4; j++)
#pragma unroll
        for (int u = 0; u < 4; u++) acc[j][u] = 0.f;

    for (int i0 = 0; i0 < HD; i0 += 32) {
        for (int t = tid; t < 64 * 32; t += 256) {
            int kk = t & 31, r = t >> 5;
            As[r][kk] = prelu_f(g_hout[(size_t)(rowbase + r) * HD + i0 + kk], a1);
        }
        for (int t = tid; t < 32 * 64; t += 256) {
            int c = t & 63, kk = t >> 6;
            Bs[kk][c] = linW[(size_t)(i0 + kk) * HD + cbase + c];
        }
        __syncthreads();
#pragma unroll
        for (int kk = 0; kk < 32; kk++) {
            float a[4];
#pragma unroll
            for (int j = 0; j < 4; j++) a[j] = As[ty * 4 + j][kk];
            float4 b = *(const float4*)&Bs[kk][tx * 4];
#pragma unroll
            for (int j = 0; j < 4; j++) {
                acc[j][0] += a[j] * b.x; acc[j][1] += a[j] * b.y;
                acc[j][2] += a[j] * b.z; acc[j][3] += a[j] * b.w;
            }
        }
        __syncthreads();
    }
#pragma unroll
    for (int j = 0; j < 4; j++) {
        int row = rowbase + ty * 4 + j;
#pragma unroll
        for (int u = 0; u < 4; u++) {
            int c = cbase + tx * 4 + u;
            out[(size_t)row * 512 + 256 + c] = prelu_f(acc[j][u] + linb[c], a2);
        }
    }
}

// ---------------- launch ----------------
extern "C" void kernel_launch(void* const* d_in, const int* in_sizes, int n_in,
                              void* d_out, int out_size) {
    (void)in_sizes; (void)n_in; (void)out_size;
    const float* obs        = (const float*)d_in[0];
    const float* comm       = (const float*)d_in[1];
    const float* obs_emb    = (const float*)d_in[2];
    const float* obs_a_emb  = (const float*)d_in[3];
    const float* obs_W      = (const float*)d_in[4];
    const float* obs_b      = (const float*)d_in[5];
    const float* obs_a      = (const float*)d_in[6];
    const float* comm_emb   = (const float*)d_in[7];
    const float* comm_a_emb = (const float*)d_in[8];
    const float* cw1 = (const float*)d_in[9];
    const float* cb1 = (const float*)d_in[10];
    const float* cw3 = (const float*)d_in[11];
    const float* cb3 = (const float*)d_in[12];
    const float* cw5 = (const float*)d_in[13];
    const float* cb5 = (const float*)d_in[14];
    const float* cw7 = (const float*)d_in[15];
    const float* cb7 = (const float*)d_in[16];
    const float* bn_g  = (const float*)d_in[17];
    const float* bn_b  = (const float*)d_in[18];
    const float* cnn_a = (const float*)d_in[19];
    const float* Wx = (const float*)d_in[20];
    const float* bx = (const float*)d_in[21];
    const float* Wh = (const float*)d_in[22];
    const float* bh = (const float*)d_in[23];
    const float* lin_a1 = (const float*)d_in[24];
    const float* lin_W  = (const float*)d_in[25];
    const float* lin_b  = (const float*)d_in[26];
    const float* lin_a2 = (const float*)d_in[27];
    float* out = (float*)d_out;

    static int smem_set = 0;
    int gru_smem = (32 * HSTR + 16 * BSTR) * (int)sizeof(float);  // 82688 B
    if (!smem_set) {
        cudaFuncSetAttribute(k_gru_persist, cudaFuncAttributeMaxDynamicSharedMemorySize, gru_smem);
        smem_set = 1;
    }

    k_zero<<<1, 256>>>();
    k_obsM<<<dim3(16, 32), 256>>>(obs_emb, obs_a_emb, obs_W);
    k_Q<<<dim3(16, 8), 256>>>(comm_emb, comm_a_emb, cw1, cw3, cw5, cw7);
    k_tok<<<32768, 128>>>(comm);
    k_obsOut<<<4096, 256>>>(obs, obs_b, obs_a, out);
    k_ypre<<<4096, 256>>>(cb1, cb3, cb5, cb7);
    k_bnfin<<<1, 256>>>(bn_g, bn_b);
    k_xproj<<<dim3(1024, 6), 256>>>(Wx, bx, cnn_a);
    k_gru_persist<<<128, 256, gru_smem>>>(Wh, bh);
    k_final<<<dim3(64, 4), 256>>>(lin_W, lin_b, lin_a1, lin_a2, out);
}

// round 8
// speedup vs baseline: 2.5652x; 2.5652x over previous
#include <cuda_runtime.h>
#include <cuda_bf16.h>
#include <cstdint>
#include <cstddef>

#define NTOT 4096
#define HD   256
#define LEN  32
#define KOBS 32
#define VOBS 128
#define VC   32
#define NL   131072   // NTOT*LEN

// ---------------- scratch (static device memory; no allocation) ----------------
__device__ float g_Mobs[KOBS * VOBS * HD];       // [k][v][h]   4 MB
__device__ float g_Q[16 * VC * 64];              // [tap][v][o] 128 KB
__device__ int   g_tok[NL];                      // argmax tokens
__device__ float g_ypre[(size_t)NL * HD];        // pre-BN conv output [n*l][h] 134 MB
__device__ float g_bnsum[HD];
__device__ float g_bnsq[HD];
__device__ float g_bnscale[HD];
__device__ float g_bnshift[HD];
__device__ float g_xp[(size_t)LEN * 3 * NTOT * HD]; // [l][g][n][h] 402 MB
__device__ float g_h[2][(size_t)NTOT * HD];      // GRU hidden (slot 0 = final)
__device__ unsigned short g_WxT[2][768 * 256];   // Wx^T bf16 hi/lo: [prec][gcol][k]
__device__ unsigned short g_WhT[2][768 * 256];   // Wh^T bf16 hi/lo
__device__ unsigned short g_Abf[2][(size_t)NL * HD]; // BN+prelu activations bf16 hi/lo

__device__ __forceinline__ float prelu_f(float x, float a) { return x >= 0.f ? x : a * x; }
__device__ __forceinline__ float sigmoidf_(float x) { return 1.f / (1.f + __expf(-x)); }

// bf16 split: x ~= hi + lo
__device__ __forceinline__ void split2u32(float x0, float x1, unsigned& hi, unsigned& lo) {
    __nv_bfloat16 h0 = __float2bfloat16(x0), h1 = __float2bfloat16(x1);
    float r0 = x0 - __bfloat162float(h0), r1 = x1 - __bfloat162float(h1);
    __nv_bfloat16 l0 = __float2bfloat16(r0), l1 = __float2bfloat16(r1);
    hi = (unsigned)__bfloat16_as_ushort(h0) | ((unsigned)__bfloat16_as_ushort(h1) << 16);
    lo = (unsigned)__bfloat16_as_ushort(l0) | ((unsigned)__bfloat16_as_ushort(l1) << 16);
}

// warp mma m16n8k16 bf16, fp32 accum (sm_80+ base feature — works on sm_103 target)
__device__ __forceinline__ void mma16816(float* d, const unsigned* a, unsigned b0, unsigned b1) {
    asm volatile(
        "mma.sync.aligned.m16n8k16.row.col.f32.bf16.bf16.f32 "
        "{%0,%1,%2,%3}, {%4,%5,%6,%7}, {%8,%9}, {%0,%1,%2,%3};"
        : "+f"(d[0]), "+f"(d[1]), "+f"(d[2]), "+f"(d[3])
        : "r"(a[0]), "r"(a[1]), "r"(a[2]), "r"(a[3]), "r"(b0), "r"(b1));
}

// ---------------- zero init ----------------
__global__ void k_zero() {
    int i = threadIdx.x;
    if (i < HD) { g_bnsum[i] = 0.f; g_bnsq[i] = 0.f; }
}

// ---------------- obs lookup table ----------------
__global__ void k_obsM(const float* __restrict__ obs_emb, const float* __restrict__ aemb_p,
                       const float* __restrict__ obs_W) {
    __shared__ float P[8 * HD];
    int k = blockIdx.y;
    int vbase = blockIdx.x * 8;
    int tid = threadIdx.x;
    float a = *aemb_p;
    for (int t = tid; t < 8 * HD; t += 256)
        P[t] = prelu_f(obs_emb[vbase * HD + t], a);
    __syncthreads();

    float acc[8];
#pragma unroll
    for (int v = 0; v < 8; v++) acc[v] = 0.f;
    const float* Wp = obs_W + (size_t)k * HD * HD + tid;
    for (int i = 0; i < HD; i++) {
        float w = Wp[(size_t)i * HD];
#pragma unroll
        for (int v = 0; v < 8; v++) acc[v] += P[v * HD + i] * w;
    }
#pragma unroll
    for (int v = 0; v < 8; v++)
        g_Mobs[((size_t)k * VOBS + vbase + v) * HD + tid] = acc[v];
}

// ---------------- conv lookup tables ----------------
__global__ void k_Q(const float* __restrict__ ce, const float* __restrict__ cap,
                    const float* __restrict__ cw1, const float* __restrict__ cw3,
                    const float* __restrict__ cw5, const float* __restrict__ cw7) {
    __shared__ float Pc[HD * VC];
    int tap = blockIdx.x, tid = threadIdx.x;
    float a = *cap;
    for (int t = tid; t < VC * HD; t += 256) {
        int v = t >> 8, i = t & 255;
        Pc[i * VC + v] = prelu_f(ce[t], a);
    }
    __syncthreads();

    int g, tt;
    if (tap == 0)       { g = 0; tt = 0; }
    else if (tap < 4)   { g = 1; tt = tap - 1; }
    else if (tap < 9)   { g = 2; tt = tap - 4; }
    else                { g = 3; tt = tap - 9; }
    int ks = 2 * g + 1;
    const float* w = (g == 0) ? cw1 : (g == 1) ? cw3 : (g == 2) ? cw5 : cw7;

    int idx = blockIdx.y * 256 + tid;
    int o = idx >> 5, v = idx & 31;
    float acc = 0.f;
    for (int i = 0; i < HD; i++)
        acc += Pc[i * VC + v] * w[((size_t)o * HD + i) * ks + tt];
    g_Q[(tap * VC + v) * 64 + o] = acc;
}

// ---------------- token argmax ----------------
__global__ void k_tok(const float* __restrict__ comm) {
    int warp = (blockIdx.x * blockDim.x + threadIdx.x) >> 5;
    int lane = threadIdx.x & 31;
    if (warp >= NL) return;
    float v = comm[(size_t)warp * VC + lane];
    int idx = lane;
#pragma unroll
    for (int off = 16; off; off >>= 1) {
        float ov = __shfl_xor_sync(0xffffffffu, v, off);
        int   oi = __shfl_xor_sync(0xffffffffu, idx, off);
        if (ov > v || (ov == v && oi < idx)) { v = ov; idx = oi; }
    }
    if (lane == 0) g_tok[warp] = idx;
}

// ---------------- obs output half ----------------
__global__ void k_obsOut(const float* __restrict__ obs, const float* __restrict__ obs_b,
                         const float* __restrict__ obs_a_p, float* __restrict__ out) {
    __shared__ int sidx[KOBS];
    __shared__ int wcnt[8];
    int n = blockIdx.x, tid = threadIdx.x;
    int flag = 0;
    if (tid < VOBS) flag = obs[(size_t)n * VOBS + tid] > 0.5f;
    unsigned mask = __ballot_sync(0xffffffffu, flag);
    int lane = tid & 31, w = tid >> 5;
    if (lane == 0) wcnt[w] = __popc(mask);
    __syncthreads();
    if (flag) {
        int base = 0;
        for (int j = 0; j < w; j++) base += wcnt[j];
        sidx[base + __popc(mask & ((1u << lane) - 1u))] = tid;
    }
    __syncthreads();

    float acc = obs_b[tid];
#pragma unroll 8
    for (int k = 0; k < KOBS; k++)
        acc += g_Mobs[((size_t)k * VOBS + sidx[k]) * HD + tid];
    out[(size_t)n * (2 * HD) + tid] = prelu_f(acc, *obs_a_p);
}

// ---------------- conv-as-lookup -> y_pre + BN partial sums ----------------
__global__ void k_ypre(const float* __restrict__ cb1, const float* __restrict__ cb3,
                       const float* __restrict__ cb5, const float* __restrict__ cb7) {
    __shared__ int tk[LEN];
    int n = blockIdx.x, tid = threadIdx.x;
    if (tid < LEN) tk[tid] = g_tok[n * LEN + tid];
    __syncthreads();

    int g = tid >> 6, o = tid & 63;
    int ks = 2 * g + 1, pad = g, base = g * g;
    const float* cbp = (g == 0) ? cb1 : (g == 1) ? cb3 : (g == 2) ? cb5 : cb7;
    float bias = cbp[o];

    float ls = 0.f, lq = 0.f;
    for (int l = 0; l < LEN; l++) {
        float acc = bias;
        for (int t = 0; t < ks; t++) {
            int lp = l + t - pad;
            if (lp >= 0 && lp < LEN)
                acc += g_Q[((base + t) * VC + tk[lp]) * 64 + o];
        }
        g_ypre[((size_t)n * LEN + l) * HD + tid] = acc;
        ls += acc; lq += acc * acc;
    }
    atomicAdd(&g_bnsum[tid], ls);
    atomicAdd(&g_bnsq[tid], lq);
}

// ---------------- BN finalize ----------------
__global__ void k_bnfin(const float* __restrict__ bn_g, const float* __restrict__ bn_b) {
    int h = threadIdx.x;
    float m   = g_bnsum[h] * (1.0f / 131072.0f);
    float var = g_bnsq[h]  * (1.0f / 131072.0f) - m * m;
    float sc  = bn_g[h] * rsqrtf(var + 1e-5f);
    g_bnscale[h] = sc;
    g_bnshift[h] = bn_b[h] - m * sc;
}

// ---------------- weight transpose+split: W[3][256][256] (g,k,n) -> [gcol][k] bf16 hi/lo ----------------
__global__ void k_Wcvt2(const float* __restrict__ W, int sel) {
    int j = blockIdx.x;      // gcol 0..767 (= g*256 + n)
    int k = threadIdx.x;     // 0..255
    float v = W[(size_t)(j >> 8) * 65536 + (size_t)k * 256 + (j & 255)];
    __nv_bfloat16 h = __float2bfloat16(v);
    float r = v - __bfloat162float(h);
    __nv_bfloat16 l = __float2bfloat16(r);
    unsigned short* hi = sel ? g_WhT[0] : g_WxT[0];
    unsigned short* lo = sel ? g_WhT[1] : g_WxT[1];
    hi[j * 256 + k] = __bfloat16_as_ushort(h);
    lo[j * 256 + k] = __bfloat16_as_ushort(l);
}

// ---------------- activations: BN + prelu + bf16 split ----------------
__global__ void k_cvtA(const float* __restrict__ cnn_a_p) {
    float ca = *cnn_a_p;
    size_t i0 = ((size_t)blockIdx.x * 256 + threadIdx.x) * 8;
    float4 v0 = *(const float4*)&g_ypre[i0];
    float4 v1 = *(const float4*)&g_ypre[i0 + 4];
    float v[8] = {v0.x, v0.y, v0.z, v0.w, v1.x, v1.y, v1.z, v1.w};
    int ch0 = (int)(i0 & 255);
    unsigned hw[4], lw[4];
#pragma unroll
    for (int e = 0; e < 4; e++) {
        float x0 = prelu_f(v[2*e]   * g_bnscale[ch0 + 2*e]   + g_bnshift[ch0 + 2*e],   ca);
        float x1 = prelu_f(v[2*e+1] * g_bnscale[ch0 + 2*e+1] + g_bnshift[ch0 + 2*e+1], ca);
        split2u32(x0, x1, hw[e], lw[e]);
    }
    *(uint4*)&g_Abf[0][i0] = make_uint4(hw[0], hw[1], hw[2], hw[3]);
    *(uint4*)&g_Abf[1][i0] = make_uint4(lw[0], lw[1], lw[2], lw[3]);
}

// ---------------- xproj via mma.sync: [131072,256] x [256,768], tiles 128x128 ----------------
// smem ushort: Ah[128][72], Al, Bh[128][72], Bl  -> 73728 B
__global__ void __launch_bounds__(256) k_xproj_mma(const float* __restrict__ bx) {
    extern __shared__ __align__(16) unsigned short sx[];
    unsigned short* Ah = sx;
    unsigned short* Al = Ah + 128 * 72;
    unsigned short* Bh = Al + 128 * 72;
    unsigned short* Bl = Bh + 128 * 72;
    int tid = threadIdx.x, wid = tid >> 5, lane = tid & 31;
    int tg = lane >> 2, tiG = lane & 3;
    int warp_m = wid >> 1, warp_n = wid & 1;
    int rowbase = blockIdx.x * 128, colbase = blockIdx.y * 128;
    int gsel = colbase >> 8;

    float acc[2][8][4];
#pragma unroll
    for (int mt = 0; mt < 2; mt++)
#pragma unroll
        for (int nt = 0; nt < 8; nt++)
#pragma unroll
            for (int u = 0; u < 4; u++) acc[mt][nt][u] = 0.f;

    for (int kc = 0; kc < 4; kc++) {
        __syncthreads();
        for (int i = tid; i < 1024; i += 256) {
            int r = i >> 3, q = i & 7;
            size_t sa = (size_t)(rowbase + r) * 256 + kc * 64 + q * 8;
            size_t sb = (size_t)(colbase + r) * 256 + kc * 64 + q * 8;
            *(uint4*)&Ah[r * 72 + q * 8] = *(const uint4*)&g_Abf[0][sa];
            *(uint4*)&Al[r * 72 + q * 8] = *(const uint4*)&g_Abf[1][sa];
            *(uint4*)&Bh[r * 72 + q * 8] = *(const uint4*)&g_WxT[0][sb];
            *(uint4*)&Bl[r * 72 + q * 8] = *(const uint4*)&g_WxT[1][sb];
        }
        __syncthreads();
#pragma unroll
        for (int ks = 0; ks < 4; ks++) {
            int k0 = ks * 16;
            unsigned ah[2][4], al[2][4];
#pragma unroll
            for (int mt = 0; mt < 2; mt++) {
                int r = warp_m * 32 + mt * 16 + tg;
                ah[mt][0] = *(const unsigned*)&Ah[r * 72 + k0 + 2 * tiG];
                ah[mt][1] = *(const unsigned*)&Ah[(r + 8) * 72 + k0 + 2 * tiG];
                ah[mt][2] = *(const unsigned*)&Ah[r * 72 + k0 + 8 + 2 * tiG];
                ah[mt][3] = *(const unsigned*)&Ah[(r + 8) * 72 + k0 + 8 + 2 * tiG];
                al[mt][0] = *(const unsigned*)&Al[r * 72 + k0 + 2 * tiG];
                al[mt][1] = *(const unsigned*)&Al[(r + 8) * 72 + k0 + 2 * tiG];
                al[mt][2] = *(const unsigned*)&Al[r * 72 + k0 + 8 + 2 * tiG];
                al[mt][3] = *(const unsigned*)&Al[(r + 8) * 72 + k0 + 8 + 2 * tiG];
            }
#pragma unroll
            for (int nt = 0; nt < 8; nt++) {
                int c = warp_n * 64 + nt * 8 + tg;
                unsigned bh0 = *(const unsigned*)&Bh[c * 72 + k0 + 2 * tiG];
                unsigned bh1 = *(const unsigned*)&Bh[c * 72 + k0 + 8 + 2 * tiG];
                unsigned bl0 = *(const unsigned*)&Bl[c * 72 + k0 + 2 * tiG];
                unsigned bl1 = *(const unsigned*)&Bl[c * 72 + k0 + 8 + 2 * tiG];
#pragma unroll
                for (int mt = 0; mt < 2; mt++) {
                    mma16816(acc[mt][nt], ah[mt], bh0, bh1);
                    mma16816(acc[mt][nt], al[mt], bh0, bh1);
                    mma16816(acc[mt][nt], ah[mt], bl0, bl1);
                }
            }
        }
    }

    // epilogue: add bias, scatter to g_xp[l][g][n][h]
#pragma unroll
    for (int mt = 0; mt < 2; mt++) {
#pragma unroll
        for (int nt = 0; nt < 8; nt++) {
            int cg = colbase + warp_n * 64 + nt * 8 + 2 * tiG;
            int hcol = cg & 255;
            float bx0 = bx[gsel * 256 + hcol], bx1 = bx[gsel * 256 + hcol + 1];
            int r0 = rowbase + warp_m * 32 + mt * 16 + tg;
            int r1 = r0 + 8;
            int n0 = r0 >> 5, l0 = r0 & 31;
            int n1 = r1 >> 5, l1 = r1 & 31;
            float2 o0 = make_float2(acc[mt][nt][0] + bx0, acc[mt][nt][1] + bx1);
            float2 o1 = make_float2(acc[mt][nt][2] + bx0, acc[mt][nt][3] + bx1);
            *(float2*)&g_xp[(((size_t)l0 * 3 + gsel) * NTOT + n0) * HD + hcol] = o0;
            *(float2*)&g_xp[(((size_t)l1 * 3 + gsel) * NTOT + n1) * HD + hcol] = o1;
        }
    }
}

// ---------------- persistent GRU via mma.sync: 128 CTAs x 32 rows ----------------
// smem: h float[32][258] (33024B) | Ah,Al ushort[32][264] (16896B ea) | Bh,Bl ushort[192][72] (27648B ea)
#define GRU_SMEM (33024 + 2 * 16896 + 2 * 27648)
__global__ void __launch_bounds__(256) k_gru_mma(const float* __restrict__ bh) {
    extern __shared__ __align__(16) char gsm[];
    float* hsh = (float*)gsm;
    unsigned short* Ah = (unsigned short*)(gsm + 33024);
    unsigned short* Al = Ah + 32 * 264;
    unsigned short* Bh = Al + 32 * 264;
    unsigned short* Bl = Bh + 192 * 72;
    int tid = threadIdx.x, wid = tid >> 5, lane = tid & 31;
    int tg = lane >> 2, tiG = lane & 3;
    int warp_m = wid >> 2, warp_n = wid & 3;
    int base = blockIdx.x * 32;

    for (int i = tid; i < 32 * 258; i += 256) hsh[i] = 0.f;

    for (int step = 0; step < LEN; step++) {
        __syncthreads();   // prior-step h writes visible
        // h -> bf16 hi/lo
        for (int i = tid; i < 4096; i += 256) {
            int r = i >> 7, cp = i & 127;
            float2 v = *(const float2*)&hsh[r * 258 + cp * 2];
            unsigned hi, lo;
            split2u32(v.x, v.y, hi, lo);
            *(unsigned*)&Ah[r * 264 + cp * 2] = hi;
            *(unsigned*)&Al[r * 264 + cp * 2] = lo;
        }
        __syncthreads();

        for (int nc = 0; nc < 4; nc++) {
            float acc[3][2][4];
#pragma unroll
            for (int g = 0; g < 3; g++)
#pragma unroll
                for (int nt = 0; nt < 2; nt++)
#pragma unroll
                    for (int u = 0; u < 4; u++) acc[g][nt][u] = 0.f;

            for (int kc = 0; kc < 4; kc++) {
                __syncthreads();   // prior frag reads done before B overwrite
                for (int i = tid; i < 1536; i += 256) {
                    int r = i >> 3, q = i & 7;
                    size_t gcol = (size_t)((r >> 6) * 256 + nc * 64 + (r & 63));
                    *(uint4*)&Bh[r * 72 + q * 8] = *(const uint4*)&g_WhT[0][gcol * 256 + kc * 64 + q * 8];
                    *(uint4*)&Bl[r * 72 + q * 8] = *(const uint4*)&g_WhT[1][gcol * 256 + kc * 64 + q * 8];
                }
                __syncthreads();
#pragma unroll
                for (int ks = 0; ks < 4; ks++) {
                    int kA = kc * 64 + ks * 16;
                    int kB = ks * 16;
                    unsigned ah[4], al[4];
                    int r = warp_m * 16 + tg;
                    ah[0] = *(const unsigned*)&Ah[r * 264 + kA + 2 * tiG];
                    ah[1] = *(const unsigned*)&Ah[(r + 8) * 264 + kA + 2 * tiG];
                    ah[2] = *(const unsigned*)&Ah[r * 264 + kA + 8 + 2 * tiG];
                    ah[3] = *(const unsigned*)&Ah[(r + 8) * 264 + kA + 8 + 2 * tiG];
                    al[0] = *(const unsigned*)&Al[r * 264 + kA + 2 * tiG];
                    al[1] = *(const unsigned*)&Al[(r + 8) * 264 + kA + 2 * tiG];
                    al[2] = *(const unsigned*)&Al[r * 264 + kA + 8 + 2 * tiG];
                    al[3] = *(const unsigned*)&Al[(r + 8) * 264 + kA + 8 + 2 * tiG];
#pragma unroll
                    for (int g = 0; g < 3; g++) {
#pragma unroll
                        for (int nt = 0; nt < 2; nt++) {
                            int br = g * 64 + warp_n * 16 + nt * 8 + tg;
                            unsigned bh0 = *(const unsigned*)&Bh[br * 72 + kB + 2 * tiG];
                            unsigned bh1 = *(const unsigned*)&Bh[br * 72 + kB + 8 + 2 * tiG];
                            unsigned bl0 = *(const unsigned*)&Bl[br * 72 + kB + 2 * tiG];
                            unsigned bl1 = *(const unsigned*)&Bl[br * 72 + kB + 8 + 2 * tiG];
                            mma16816(acc[g][nt], ah, bh0, bh1);
                            mma16816(acc[g][nt], al, bh0, bh1);
                            mma16816(acc[g][nt], ah, bl0, bl1);
                        }
                    }
                }
            }

            // gate math for this col chunk; each thread owns its (row, col) cells
#pragma unroll
            for (int nt = 0; nt < 2; nt++) {
                int ccol = nc * 64 + warp_n * 16 + nt * 8 + 2 * tiG;
                float2 br2 = *(const float2*)&bh[ccol];
                float2 bz2 = *(const float2*)&bh[256 + ccol];
                float2 bn2 = *(const float2*)&bh[512 + ccol];
#pragma unroll
                for (int half = 0; half < 2; half++) {
                    int r = warp_m * 16 + tg + half * 8;
                    int grow = base + r;
                    int ai = half * 2;
                    size_t xb = (((size_t)step * 3) * NTOT + grow) * HD + ccol;
                    float2 xr = *(const float2*)&g_xp[xb];
                    float2 xz = *(const float2*)&g_xp[xb + (size_t)NTOT * HD];
                    float2 xn = *(const float2*)&g_xp[xb + 2 * (size_t)NTOT * HD];
                    float2 ho = *(const float2*)&hsh[r * 258 + ccol];
                    float rr0 = sigmoidf_(xr.x + acc[0][nt][ai]     + br2.x);
                    float rr1 = sigmoidf_(xr.y + acc[0][nt][ai + 1] + br2.y);
                    float zz0 = sigmoidf_(xz.x + acc[1][nt][ai]     + bz2.x);
                    float zz1 = sigmoidf_(xz.y + acc[1][nt][ai + 1] + bz2.y);
                    float nn0 = tanhf(xn.x + rr0 * (acc[2][nt][ai]     + bn2.x));
                    float nn1 = tanhf(xn.y + rr1 * (acc[2][nt][ai + 1] + bn2.y));
                    float2 hn;
                    hn.x = nn0 * (1.f - zz0) + ho.x * zz0;
                    hn.y = nn1 * (1.f - zz1) + ho.y * zz1;
                    *(float2*)&hsh[r * 258 + ccol] = hn;
                }
            }
        }
    }
    __syncthreads();
    for (int i = tid; i < 32 * HD; i += 256) {
        int r = i >> 8, c = i & 255;
        g_h[0][(size_t)(base + r) * HD + c] = hsh[r * 258 + c];
    }
}

// ---------------- final linear ----------------
__global__ void k_final(const float* __restrict__ linW, const float* __restrict__ linb,
                        const float* __restrict__ a1p, const float* __restrict__ a2p,
                        float* __restrict__ out) {
    __shared__ __align__(16) float As[64][33];
    __shared__ __align__(16) float Bs[32][64];
    float a1 = *a1p, a2 = *a2p;
    int tid = threadIdx.x;
    int rowbase = blockIdx.x * 64, cbase = blockIdx.y * 64;
    int tx = tid & 15, ty = tid >> 4;

    float acc[4][4];
#pragma unroll
    for (int j = 0; j < 4; j++)
#pragma unroll
        for (int u = 0; u < 4; u++) acc[j][u] = 0.f;

    for (int i0 = 0; i0 < HD; i0 += 32) {
        for (int t = tid; t < 64 * 32; t += 256) {
            int kk = t & 31, r = t >> 5;
            As[r][kk] = prelu_f(g_h[0][(size_t)(rowbase + r) * HD + i0 + kk], a1);
        }
        for (int t = tid; t < 32 * 64; t += 256) {
            int c = t & 63, kk = t >> 6;
            Bs[kk][c] = linW[(size_t)(i0 + kk) * HD + cbase + c];
        }
        __syncthreads();
#pragma unroll
        for (int kk = 0; kk < 32; kk++) {
            float a[4];
#pragma unroll
            for (int j = 0; j < 4; j++) a[j] = As[ty * 4 + j][kk];
            float4 b = *(const float4*)&Bs[kk][tx * 4];
#pragma unroll
            for (int j = 0; j < 4; j++) {
                acc[j][0] += a[j] * b.x; acc[j][1] += a[j] * b.y;
                acc[j][2] += a[j] * b.z; acc[j][3] += a[j] * b.w;
            }
        }
        __syncthreads();
    }
#pragma unroll
    for (int j = 0; j < 4; j++) {
        int row = rowbase + ty * 4 + j;
#pragma unroll
        for (int u = 0; u < 4; u++) {
            int c = cbase + tx * 4 + u;
            out[(size_t)row * 512 + 256 + c] = prelu_f(acc[j][u] + linb[c], a2);
        }
    }
}

// ---------------- launch ----------------
extern "C" void kernel_launch(void* const* d_in, const int* in_sizes, int n_in,
                              void* d_out, int out_size) {
    (void)in_sizes; (void)n_in; (void)out_size;
    const float* obs        = (const float*)d_in[0];
    const float* comm       = (const float*)d_in[1];
    const float* obs_emb    = (const float*)d_in[2];
    const float* obs_a_emb  = (const float*)d_in[3];
    const float* obs_W      = (const float*)d_in[4];
    const float* obs_b      = (const float*)d_in[5];
    const float* obs_a      = (const float*)d_in[6];
    const float* comm_emb   = (const float*)d_in[7];
    const float* comm_a_emb = (const float*)d_in[8];
    const float* cw1 = (const float*)d_in[9];
    const float* cb1 = (const float*)d_in[10];
    const float* cw3 = (const float*)d_in[11];
    const float* cb3 = (const float*)d_in[12];
    const float* cw5 = (const float*)d_in[13];
    const float* cb5 = (const float*)d_in[14];
    const float* cw7 = (const float*)d_in[15];
    const float* cb7 = (const float*)d_in[16];
    const float* bn_g  = (const float*)d_in[17];
    const float* bn_b  = (const float*)d_in[18];
    const float* cnn_a = (const float*)d_in[19];
    const float* Wx = (const float*)d_in[20];
    const float* bx = (const float*)d_in[21];
    const float* Wh = (const float*)d_in[22];
    const float* bh = (const float*)d_in[23];
    const float* lin_a1 = (const float*)d_in[24];
    const float* lin_W  = (const float*)d_in[25];
    const float* lin_b  = (const float*)d_in[26];
    const float* lin_a2 = (const float*)d_in[27];
    float* out = (float*)d_out;

    static int attr_set = 0;
    if (!attr_set) {
        cudaFuncSetAttribute(k_xproj_mma, cudaFuncAttributeMaxDynamicSharedMemorySize, 73728);
        cudaFuncSetAttribute(k_gru_mma, cudaFuncAttributeMaxDynamicSharedMemorySize, GRU_SMEM);
        attr_set = 1;
    }

    k_zero<<<1, 256>>>();
    k_obsM<<<dim3(16, 32), 256>>>(obs_emb, obs_a_emb, obs_W);
    k_Q<<<dim3(16, 8), 256>>>(comm_emb, comm_a_emb, cw1, cw3, cw5, cw7);
    k_tok<<<32768, 128>>>(comm);
    k_obsOut<<<4096, 256>>>(obs, obs_b, obs_a, out);
    k_ypre<<<4096, 256>>>(cb1, cb3, cb5, cb7);
    k_bnfin<<<1, 256>>>(bn_g, bn_b);
    k_Wcvt2<<<768, 256>>>(Wx, 0);
    k_Wcvt2<<<768, 256>>>(Wh, 1);
    k_cvtA<<<16384, 256>>>(cnn_a);
    k_xproj_mma<<<dim3(1024, 6), 256, 73728>>>(bx);
    k_gru_mma<<<128, 256, GRU_SMEM>>>(bh);
    k_final<<<dim3(64, 4), 256>>>(lin_W, lin_b, lin_a1, lin_a2, out);
}

// round 9
// speedup vs baseline: 2.8563x; 1.1135x over previous
#include <cuda_runtime.h>
#include <cuda_bf16.h>
#include <cstdint>
#include <cstddef>

#define NTOT 4096
#define HD   256
#define LEN  32
#define KOBS 32
#define VOBS 128
#define VC   32
#define NL   131072   // NTOT*LEN

// ---------------- scratch (static device memory; no allocation) ----------------
__device__ float g_Mobs[KOBS * VOBS * HD];       // [k][v][h]   4 MB
__device__ float g_Q[16 * VC * 64];              // [tap][v][o] 128 KB
__device__ int   g_tok[NL];                      // argmax tokens
__device__ float g_ypre[(size_t)NL * HD];        // pre-BN conv output [n*l][h] 134 MB
__device__ float g_bnsum[HD];
__device__ float g_bnsq[HD];
__device__ float g_bnscale[HD];
__device__ float g_bnshift[HD];
__device__ float g_xp[(size_t)LEN * 3 * NTOT * HD]; // [l][g][n][h] 402 MB
__device__ float g_h[2][(size_t)NTOT * HD];      // GRU hidden (slot 0 = final)
__device__ unsigned short g_WxT[2][768 * 256];   // Wx^T bf16 hi/lo: [prec][gcol][k]
__device__ unsigned short g_WhT[2][768 * 256];   // Wh^T bf16 hi/lo
__device__ unsigned short g_Abf[2][(size_t)NL * HD]; // BN+prelu activations bf16 hi/lo

__device__ __forceinline__ float prelu_f(float x, float a) { return x >= 0.f ? x : a * x; }
__device__ __forceinline__ float sigmoidf_(float x) { return 1.f / (1.f + __expf(-x)); }

__device__ __forceinline__ uint32_t smem_u32(const void* p) {
    uint32_t a;
    asm("{ .reg .u64 t; cvta.to.shared.u64 t, %1; cvt.u32.u64 %0, t; }" : "=r"(a) : "l"(p));
    return a;
}

// bf16 split: x ~= hi + lo
__device__ __forceinline__ void split2u32(float x0, float x1, unsigned& hi, unsigned& lo) {
    __nv_bfloat16 h0 = __float2bfloat16(x0), h1 = __float2bfloat16(x1);
    float r0 = x0 - __bfloat162float(h0), r1 = x1 - __bfloat162float(h1);
    __nv_bfloat16 l0 = __float2bfloat16(r0), l1 = __float2bfloat16(r1);
    hi = (unsigned)__bfloat16_as_ushort(h0) | ((unsigned)__bfloat16_as_ushort(h1) << 16);
    lo = (unsigned)__bfloat16_as_ushort(l0) | ((unsigned)__bfloat16_as_ushort(l1) << 16);
}

// warp mma m16n8k16 bf16, fp32 accum (sm_80+ base feature)
__device__ __forceinline__ void mma16816(float* d, const unsigned* a, unsigned b0, unsigned b1) {
    asm volatile(
        "mma.sync.aligned.m16n8k16.row.col.f32.bf16.bf16.f32 "
        "{%0,%1,%2,%3}, {%4,%5,%6,%7}, {%8,%9}, {%0,%1,%2,%3};"
        : "+f"(d[0]), "+f"(d[1]), "+f"(d[2]), "+f"(d[3])
        : "r"(a[0]), "r"(a[1]), "r"(a[2]), "r"(a[3]), "r"(b0), "r"(b1));
}

#define CP_ASYNC16(dst_u32, src_ptr) \
    asm volatile("cp.async.cg.shared.global [%0], [%1], 16;" :: "r"(dst_u32), "l"(src_ptr))
#define CP_COMMIT() asm volatile("cp.async.commit_group;" ::: "memory")
#define CP_WAIT0()  asm volatile("cp.async.wait_group 0;" ::: "memory")

// ---------------- zero init ----------------
__global__ void k_zero() {
    int i = threadIdx.x;
    if (i < HD) { g_bnsum[i] = 0.f; g_bnsq[i] = 0.f; }
}

// ---------------- obs lookup table ----------------
__global__ void k_obsM(const float* __restrict__ obs_emb, const float* __restrict__ aemb_p,
                       const float* __restrict__ obs_W) {
    __shared__ float P[8 * HD];
    int k = blockIdx.y;
    int vbase = blockIdx.x * 8;
    int tid = threadIdx.x;
    float a = *aemb_p;
    for (int t = tid; t < 8 * HD; t += 256)
        P[t] = prelu_f(obs_emb[vbase * HD + t], a);
    __syncthreads();

    float acc[8];
#pragma unroll
    for (int v = 0; v < 8; v++) acc[v] = 0.f;
    const float* Wp = obs_W + (size_t)k * HD * HD + tid;
    for (int i = 0; i < HD; i++) {
        float w = Wp[(size_t)i * HD];
#pragma unroll
        for (int v = 0; v < 8; v++) acc[v] += P[v * HD + i] * w;
    }
#pragma unroll
    for (int v = 0; v < 8; v++)
        g_Mobs[((size_t)k * VOBS + vbase + v) * HD + tid] = acc[v];
}

// ---------------- conv lookup tables ----------------
__global__ void k_Q(const float* __restrict__ ce, const float* __restrict__ cap,
                    const float* __restrict__ cw1, const float* __restrict__ cw3,
                    const float* __restrict__ cw5, const float* __restrict__ cw7) {
    __shared__ float Pc[HD * VC];
    int tap = blockIdx.x, tid = threadIdx.x;
    float a = *cap;
    for (int t = tid; t < VC * HD; t += 256) {
        int v = t >> 8, i = t & 255;
        Pc[i * VC + v] = prelu_f(ce[t], a);
    }
    __syncthreads();

    int g, tt;
    if (tap == 0)       { g = 0; tt = 0; }
    else if (tap < 4)   { g = 1; tt = tap - 1; }
    else if (tap < 9)   { g = 2; tt = tap - 4; }
    else                { g = 3; tt = tap - 9; }
    int ks = 2 * g + 1;
    const float* w = (g == 0) ? cw1 : (g == 1) ? cw3 : (g == 2) ? cw5 : cw7;

    int idx = blockIdx.y * 256 + tid;
    int o = idx >> 5, v = idx & 31;
    float acc = 0.f;
    for (int i = 0; i < HD; i++)
        acc += Pc[i * VC + v] * w[((size_t)o * HD + i) * ks + tt];
    g_Q[(tap * VC + v) * 64 + o] = acc;
}

// ---------------- token argmax ----------------
__global__ void k_tok(const float* __restrict__ comm) {
    int warp = (blockIdx.x * blockDim.x + threadIdx.x) >> 5;
    int lane = threadIdx.x & 31;
    if (warp >= NL) return;
    float v = comm[(size_t)warp * VC + lane];
    int idx = lane;
#pragma unroll
    for (int off = 16; off; off >>= 1) {
        float ov = __shfl_xor_sync(0xffffffffu, v, off);
        int   oi = __shfl_xor_sync(0xffffffffu, idx, off);
        if (ov > v || (ov == v && oi < idx)) { v = ov; idx = oi; }
    }
    if (lane == 0) g_tok[warp] = idx;
}

// ---------------- obs output half ----------------
__global__ void k_obsOut(const float* __restrict__ obs, const float* __restrict__ obs_b,
                         const float* __restrict__ obs_a_p, float* __restrict__ out) {
    __shared__ int sidx[KOBS];
    __shared__ int wcnt[8];
    int n = blockIdx.x, tid = threadIdx.x;
    int flag = 0;
    if (tid < VOBS) flag = obs[(size_t)n * VOBS + tid] > 0.5f;
    unsigned mask = __ballot_sync(0xffffffffu, flag);
    int lane = tid & 31, w = tid >> 5;
    if (lane == 0) wcnt[w] = __popc(mask);
    __syncthreads();
    if (flag) {
        int base = 0;
        for (int j = 0; j < w; j++) base += wcnt[j];
        sidx[base + __popc(mask & ((1u << lane) - 1u))] = tid;
    }
    __syncthreads();

    float acc = obs_b[tid];
#pragma unroll 8
    for (int k = 0; k < KOBS; k++)
        acc += g_Mobs[((size_t)k * VOBS + sidx[k]) * HD + tid];
    out[(size_t)n * (2 * HD) + tid] = prelu_f(acc, *obs_a_p);
}

// ---------------- conv-as-lookup -> y_pre + BN partial sums ----------------
__global__ void k_ypre(const float* __restrict__ cb1, const float* __restrict__ cb3,
                       const float* __restrict__ cb5, const float* __restrict__ cb7) {
    __shared__ int tk[LEN];
    int n = blockIdx.x, tid = threadIdx.x;
    if (tid < LEN) tk[tid] = g_tok[n * LEN + tid];
    __syncthreads();

    int g = tid >> 6, o = tid & 63;
    int ks = 2 * g + 1, pad = g, base = g * g;
    const float* cbp = (g == 0) ? cb1 : (g == 1) ? cb3 : (g == 2) ? cb5 : cb7;
    float bias = cbp[o];

    float ls = 0.f, lq = 0.f;
    for (int l = 0; l < LEN; l++) {
        float acc = bias;
        for (int t = 0; t < ks; t++) {
            int lp = l + t - pad;
            if (lp >= 0 && lp < LEN)
                acc += g_Q[((base + t) * VC + tk[lp]) * 64 + o];
        }
        g_ypre[((size_t)n * LEN + l) * HD + tid] = acc;
        ls += acc; lq += acc * acc;
    }
    atomicAdd(&g_bnsum[tid], ls);
    atomicAdd(&g_bnsq[tid], lq);
}

// ---------------- BN finalize ----------------
__global__ void k_bnfin(const float* __restrict__ bn_g, const float* __restrict__ bn_b) {
    int h = threadIdx.x;
    float m   = g_bnsum[h] * (1.0f / 131072.0f);
    float var = g_bnsq[h]  * (1.0f / 131072.0f) - m * m;
    float sc  = bn_g[h] * rsqrtf(var + 1e-5f);
    g_bnscale[h] = sc;
    g_bnshift[h] = bn_b[h] - m * sc;
}

// ---------------- weight transpose+split: W[3][256][256] (g,k,n) -> [gcol][k] bf16 hi/lo ----------------
__global__ void k_Wcvt2(const float* __restrict__ W, int sel) {
    int j = blockIdx.x;      // gcol 0..767 (= g*256 + n)
    int k = threadIdx.x;     // 0..255
    float v = W[(size_t)(j >> 8) * 65536 + (size_t)k * 256 + (j & 255)];
    __nv_bfloat16 h = __float2bfloat16(v);
    float r = v - __bfloat162float(h);
    __nv_bfloat16 l = __float2bfloat16(r);
    unsigned short* hi = sel ? g_WhT[0] : g_WxT[0];
    unsigned short* lo = sel ? g_WhT[1] : g_WxT[1];
    hi[j * 256 + k] = __bfloat16_as_ushort(h);
    lo[j * 256 + k] = __bfloat16_as_ushort(l);
}

// ---------------- activations: BN + prelu + bf16 split ----------------
__global__ void k_cvtA(const float* __restrict__ cnn_a_p) {
    float ca = *cnn_a_p;
    size_t i0 = ((size_t)blockIdx.x * 256 + threadIdx.x) * 8;
    float4 v0 = *(const float4*)&g_ypre[i0];
    float4 v1 = *(const float4*)&g_ypre[i0 + 4];
    float v[8] = {v0.x, v0.y, v0.z, v0.w, v1.x, v1.y, v1.z, v1.w};
    int ch0 = (int)(i0 & 255);
    unsigned hw[4], lw[4];
#pragma unroll
    for (int e = 0; e < 4; e++) {
        float x0 = prelu_f(v[2*e]   * g_bnscale[ch0 + 2*e]   + g_bnshift[ch0 + 2*e],   ca);
        float x1 = prelu_f(v[2*e+1] * g_bnscale[ch0 + 2*e+1] + g_bnshift[ch0 + 2*e+1], ca);
        split2u32(x0, x1, hw[e], lw[e]);
    }
    *(uint4*)&g_Abf[0][i0] = make_uint4(hw[0], hw[1], hw[2], hw[3]);
    *(uint4*)&g_Abf[1][i0] = make_uint4(lw[0], lw[1], lw[2], lw[3]);
}

// ---------------- xproj via mma.sync: [131072,256] x [256,768], tiles 128x128 ----------------
// grid (6, 1024): x = coltile (fast-varying -> A tile L2 reuse), y = rowtile
__global__ void __launch_bounds__(256) k_xproj_mma(const float* __restrict__ bx) {
    extern __shared__ __align__(16) unsigned short sx[];
    unsigned short* Ah = sx;
    unsigned short* Al = Ah + 128 * 72;
    unsigned short* Bh = Al + 128 * 72;
    unsigned short* Bl = Bh + 128 * 72;
    int tid = threadIdx.x, wid = tid >> 5, lane = tid & 31;
    int tg = lane >> 2, tiG = lane & 3;
    int warp_m = wid >> 1, warp_n = wid & 1;
    int rowbase = blockIdx.y * 128, colbase = blockIdx.x * 128;
    int gsel = colbase >> 8;

    float acc[2][8][4];
#pragma unroll
    for (int mt = 0; mt < 2; mt++)
#pragma unroll
        for (int nt = 0; nt < 8; nt++)
#pragma unroll
            for (int u = 0; u < 4; u++) acc[mt][nt][u] = 0.f;

    for (int kc = 0; kc < 4; kc++) {
        __syncthreads();
        for (int i = tid; i < 1024; i += 256) {
            int r = i >> 3, q = i & 7;
            size_t sa = (size_t)(rowbase + r) * 256 + kc * 64 + q * 8;
            size_t sb = (size_t)(colbase + r) * 256 + kc * 64 + q * 8;
            *(uint4*)&Ah[r * 72 + q * 8] = *(const uint4*)&g_Abf[0][sa];
            *(uint4*)&Al[r * 72 + q * 8] = *(const uint4*)&g_Abf[1][sa];
            *(uint4*)&Bh[r * 72 + q * 8] = *(const uint4*)&g_WxT[0][sb];
            *(uint4*)&Bl[r * 72 + q * 8] = *(const uint4*)&g_WxT[1][sb];
        }
        __syncthreads();
#pragma unroll
        for (int ks = 0; ks < 4; ks++) {
            int k0 = ks * 16;
            unsigned ah[2][4], al[2][4];
#pragma unroll
            for (int mt = 0; mt < 2; mt++) {
                int r = warp_m * 32 + mt * 16 + tg;
                ah[mt][0] = *(const unsigned*)&Ah[r * 72 + k0 + 2 * tiG];
                ah[mt][1] = *(const unsigned*)&Ah[(r + 8) * 72 + k0 + 2 * tiG];
                ah[mt][2] = *(const unsigned*)&Ah[r * 72 + k0 + 8 + 2 * tiG];
                ah[mt][3] = *(const unsigned*)&Ah[(r + 8) * 72 + k0 + 8 + 2 * tiG];
                al[mt][0] = *(const unsigned*)&Al[r * 72 + k0 + 2 * tiG];
                al[mt][1] = *(const unsigned*)&Al[(r + 8) * 72 + k0 + 2 * tiG];
                al[mt][2] = *(const unsigned*)&Al[r * 72 + k0 + 8 + 2 * tiG];
                al[mt][3] = *(const unsigned*)&Al[(r + 8) * 72 + k0 + 8 + 2 * tiG];
            }
#pragma unroll
            for (int nt = 0; nt < 8; nt++) {
                int c = warp_n * 64 + nt * 8 + tg;
                unsigned bh0 = *(const unsigned*)&Bh[c * 72 + k0 + 2 * tiG];
                unsigned bh1 = *(const unsigned*)&Bh[c * 72 + k0 + 8 + 2 * tiG];
                unsigned bl0 = *(const unsigned*)&Bl[c * 72 + k0 + 2 * tiG];
                unsigned bl1 = *(const unsigned*)&Bl[c * 72 + k0 + 8 + 2 * tiG];
#pragma unroll
                for (int mt = 0; mt < 2; mt++) {
                    mma16816(acc[mt][nt], ah[mt], bh0, bh1);
                    mma16816(acc[mt][nt], al[mt], bh0, bh1);
                    mma16816(acc[mt][nt], ah[mt], bl0, bl1);
                }
            }
        }
    }

    // epilogue: add bias, scatter to g_xp[l][g][n][h]
#pragma unroll
    for (int mt = 0; mt < 2; mt++) {
#pragma unroll
        for (int nt = 0; nt < 8; nt++) {
            int cg = colbase + warp_n * 64 + nt * 8 + 2 * tiG;
            int hcol = cg & 255;
            float bx0 = bx[gsel * 256 + hcol], bx1 = bx[gsel * 256 + hcol + 1];
            int r0 = rowbase + warp_m * 32 + mt * 16 + tg;
            int r1 = r0 + 8;
            int n0 = r0 >> 5, l0 = r0 & 31;
            int n1 = r1 >> 5, l1 = r1 & 31;
            float2 o0 = make_float2(acc[mt][nt][0] + bx0, acc[mt][nt][1] + bx1);
            float2 o1 = make_float2(acc[mt][nt][2] + bx0, acc[mt][nt][3] + bx1);
            *(float2*)&g_xp[(((size_t)l0 * 3 + gsel) * NTOT + n0) * HD + hcol] = o0;
            *(float2*)&g_xp[(((size_t)l1 * 3 + gsel) * NTOT + n1) * HD + hcol] = o1;
        }
    }
}

// ---------------- persistent GRU via mma.sync + cp.async double-buffered B ----------------
// smem: h float[32][258] (33024B) | Ah,Al ushort[32][264] (16896B ea)
//       | 2 stage bufs, each {Bh,Bl} ushort[192][72] (27648B ea) = 55296B/stage
#define GRU_H_BYTES   33024
#define GRU_A_BYTES   (2 * 16896)
#define GRU_STG_BYTES 55296
#define GRU_SMEM (GRU_H_BYTES + GRU_A_BYTES + 2 * GRU_STG_BYTES)   // 177408
__global__ void __launch_bounds__(256) k_gru_mma(const float* __restrict__ bh) {
    extern __shared__ __align__(16) char gsm[];
    float* hsh = (float*)gsm;
    unsigned short* Ah = (unsigned short*)(gsm + GRU_H_BYTES);
    unsigned short* Al = Ah + 32 * 264;
    char* bstage = gsm + GRU_H_BYTES + GRU_A_BYTES;
    int tid = threadIdx.x, wid = tid >> 5, lane = tid & 31;
    int tg = lane >> 2, tiG = lane & 3;
    int warp_m = wid >> 2, warp_n = wid & 3;
    int base = blockIdx.x * 32;

    for (int i = tid; i < 32 * 258; i += 256) hsh[i] = 0.f;

    for (int step = 0; step < LEN; step++) {
        __syncthreads();   // prior-step h writes visible; stage bufs free

        // issue stage 0 load (overlaps with h conversion)
        {
            int nc_ = 0, kc_ = 0;
            char* dst = bstage + 0;
#pragma unroll
            for (int prec = 0; prec < 2; prec++)
                for (int i = tid; i < 1536; i += 256) {
                    int r = i >> 3, q = i & 7;
                    int gcol = (r >> 6) * 256 + nc_ * 64 + (r & 63);
                    const unsigned short* src = &g_WhT[prec][(size_t)gcol * 256 + kc_ * 64 + q * 8];
                    CP_ASYNC16(smem_u32(dst + prec * 27648 + r * 144 + q * 16), src);
                }
            CP_COMMIT();
        }

        // h -> bf16 hi/lo
        for (int i = tid; i < 4096; i += 256) {
            int r = i >> 7, cp = i & 127;
            float2 v = *(const float2*)&hsh[r * 258 + cp * 2];
            unsigned hi, lo;
            split2u32(v.x, v.y, hi, lo);
            *(unsigned*)&Ah[r * 264 + cp * 2] = hi;
            *(unsigned*)&Al[r * 264 + cp * 2] = lo;
        }
        __syncthreads();   // A ready

        for (int nc = 0; nc < 4; nc++) {
            float acc[3][2][4];
#pragma unroll
            for (int g = 0; g < 3; g++)
#pragma unroll
                for (int nt = 0; nt < 2; nt++)
#pragma unroll
                    for (int u = 0; u < 4; u++) acc[g][nt][u] = 0.f;

            for (int kc = 0; kc < 4; kc++) {
                int s = nc * 4 + kc;
                CP_WAIT0();        // stage s data arrived
                __syncthreads();   // all warps done with stage s-1 buffer
                if (s < 15) {      // prefetch stage s+1 into the other buffer
                    int s1 = s + 1;
                    int nc_ = s1 >> 2, kc_ = s1 & 3;
                    char* dst = bstage + (s1 & 1) * GRU_STG_BYTES;
#pragma unroll
                    for (int prec = 0; prec < 2; prec++)
                        for (int i = tid; i < 1536; i += 256) {
                            int r = i >> 3, q = i & 7;
                            int gcol = (r >> 6) * 256 + nc_ * 64 + (r & 63);
                            const unsigned short* src = &g_WhT[prec][(size_t)gcol * 256 + kc_ * 64 + q * 8];
                            CP_ASYNC16(smem_u32(dst + prec * 27648 + r * 144 + q * 16), src);
                        }
                    CP_COMMIT();
                }

                unsigned short* Bh = (unsigned short*)(bstage + (s & 1) * GRU_STG_BYTES);
                unsigned short* Bl = Bh + 13824;
#pragma unroll
                for (int ks = 0; ks < 4; ks++) {
                    int kA = kc * 64 + ks * 16;
                    int kB = ks * 16;
                    unsigned ah[4], al[4];
                    int r = warp_m * 16 + tg;
                    ah[0] = *(const unsigned*)&Ah[r * 264 + kA + 2 * tiG];
                    ah[1] = *(const unsigned*)&Ah[(r + 8) * 264 + kA + 2 * tiG];
                    ah[2] = *(const unsigned*)&Ah[r * 264 + kA + 8 + 2 * tiG];
                    ah[3] = *(const unsigned*)&Ah[(r + 8) * 264 + kA + 8 + 2 * tiG];
                    al[0] = *(const unsigned*)&Al[r * 264 + kA + 2 * tiG];
                    al[1] = *(const unsigned*)&Al[(r + 8) * 264 + kA + 2 * tiG];
                    al[2] = *(const unsigned*)&Al[r * 264 + kA + 8 + 2 * tiG];
                    al[3] = *(const unsigned*)&Al[(r + 8) * 264 + kA + 8 + 2 * tiG];
#pragma unroll
                    for (int g = 0; g < 3; g++) {
#pragma unroll
                        for (int nt = 0; nt < 2; nt++) {
                            int br = g * 64 + warp_n * 16 + nt * 8 + tg;
                            unsigned bh0 = *(const unsigned*)&Bh[br * 72 + kB + 2 * tiG];
                            unsigned bh1 = *(const unsigned*)&Bh[br * 72 + kB + 8 + 2 * tiG];
                            unsigned bl0 = *(const unsigned*)&Bl[br * 72 + kB + 2 * tiG];
                            unsigned bl1 = *(const unsigned*)&Bl[br * 72 + kB + 8 + 2 * tiG];
                            mma16816(acc[g][nt], ah, bh0, bh1);
                            mma16816(acc[g][nt], al, bh0, bh1);
                            mma16816(acc[g][nt], ah, bl0, bl1);
                        }
                    }
                }
            }

            // gate math for this col chunk; each thread owns its (row, col) cells
#pragma unroll
            for (int nt = 0; nt < 2; nt++) {
                int ccol = nc * 64 + warp_n * 16 + nt * 8 + 2 * tiG;
                float2 br2 = *(const float2*)&bh[ccol];
                float2 bz2 = *(const float2*)&bh[256 + ccol];
                float2 bn2 = *(const float2*)&bh[512 + ccol];
#pragma unroll
                for (int half = 0; half < 2; half++) {
                    int r = warp_m * 16 + tg + half * 8;
                    int grow = base + r;
                    int ai = half * 2;
                    size_t xb = (((size_t)step * 3) * NTOT + grow) * HD + ccol;
                    float2 xr = *(const float2*)&g_xp[xb];
                    float2 xz = *(const float2*)&g_xp[xb + (size_t)NTOT * HD];
                    float2 xn = *(const float2*)&g_xp[xb + 2 * (size_t)NTOT * HD];
                    float2 ho = *(const float2*)&hsh[r * 258 + ccol];
                    float rr0 = sigmoidf_(xr.x + acc[0][nt][ai]     + br2.x);
                    float rr1 = sigmoidf_(xr.y + acc[0][nt][ai + 1] + br2.y);
                    float zz0 = sigmoidf_(xz.x + acc[1][nt][ai]     + bz2.x);
                    float zz1 = sigmoidf_(xz.y + acc[1][nt][ai + 1] + bz2.y);
                    float nn0 = tanhf(xn.x + rr0 * (acc[2][nt][ai]     + bn2.x));
                    float nn1 = tanhf(xn.y + rr1 * (acc[2][nt][ai + 1] + bn2.y));
                    float2 hn;
                    hn.x = nn0 * (1.f - zz0) + ho.x * zz0;
                    hn.y = nn1 * (1.f - zz1) + ho.y * zz1;
                    *(float2*)&hsh[r * 258 + ccol] = hn;
                }
            }
        }
    }
    __syncthreads();
    for (int i = tid; i < 32 * HD; i += 256) {
        int r = i >> 8, c = i & 255;
        g_h[0][(size_t)(base + r) * HD + c] = hsh[r * 258 + c];
    }
}

// ---------------- final linear ----------------
__global__ void k_final(const float* __restrict__ linW, const float* __restrict__ linb,
                        const float* __restrict__ a1p, const float* __restrict__ a2p,
                        float* __restrict__ out) {
    __shared__ __align__(16) float As[64][33];
    __shared__ __align__(16) float Bs[32][64];
    float a1 = *a1p, a2 = *a2p;
    int tid = threadIdx.x;
    int rowbase = blockIdx.x * 64, cbase = blockIdx.y * 64;
    int tx = tid & 15, ty = tid >> 4;

    float acc[4][4];
#pragma unroll
    for (int j = 0; j < 4; j++)
#pragma unroll
        for (int u = 0; u < 4; u++) acc[j][u] = 0.f;

    for (int i0 = 0; i0 < HD; i0 += 32) {
        for (int t = tid; t < 64 * 32; t += 256) {
            int kk = t & 31, r = t >> 5;
            As[r][kk] = prelu_f(g_h[0][(size_t)(rowbase + r) * HD + i0 + kk], a1);
        }
        for (int t = tid; t < 32 * 64; t += 256) {
            int c = t & 63, kk = t >> 6;
            Bs[kk][c] = linW[(size_t)(i0 + kk) * HD + cbase + c];
        }
        __syncthreads();
#pragma unroll
        for (int kk = 0; kk < 32; kk++) {
            float a[4];
#pragma unroll
            for (int j = 0; j < 4; j++) a[j] = As[ty * 4 + j][kk];
            float4 b = *(const float4*)&Bs[kk][tx * 4];
#pragma unroll
            for (int j = 0; j < 4; j++) {
                acc[j][0] += a[j] * b.x; acc[j][1] += a[j] * b.y;
                acc[j][2] += a[j] * b.z; acc[j][3] += a[j] * b.w;
            }
        }
        __syncthreads();
    }
#pragma unroll
    for (int j = 0; j < 4; j++) {
        int row = rowbase + ty * 4 + j;
#pragma unroll
        for (int u = 0; u < 4; u++) {
            int c = cbase + tx * 4 + u;
            out[(size_t)row * 512 + 256 + c] = prelu_f(acc[j][u] + linb[c], a2);
        }
    }
}

// ---------------- launch ----------------
extern "C" void kernel_launch(void* const* d_in, const int* in_sizes, int n_in,
                              void* d_out, int out_size) {
    (void)in_sizes; (void)n_in; (void)out_size;
    const float* obs        = (const float*)d_in[0];
    const float* comm       = (const float*)d_in[1];
    const float* obs_emb    = (const float*)d_in[2];
    const float* obs_a_emb  = (const float*)d_in[3];
    const float* obs_W      = (const float*)d_in[4];
    const float* obs_b      = (const float*)d_in[5];
    const float* obs_a      = (const float*)d_in[6];
    const float* comm_emb   = (const float*)d_in[7];
    const float* comm_a_emb = (const float*)d_in[8];
    const float* cw1 = (const float*)d_in[9];
    const float* cb1 = (const float*)d_in[10];
    const float* cw3 = (const float*)d_in[11];
    const float* cb3 = (const float*)d_in[12];
    const float* cw5 = (const float*)d_in[13];
    const float* cb5 = (const float*)d_in[14];
    const float* cw7 = (const float*)d_in[15];
    const float* cb7 = (const float*)d_in[16];
    const float* bn_g  = (const float*)d_in[17];
    const float* bn_b  = (const float*)d_in[18];
    const float* cnn_a = (const float*)d_in[19];
    const float* Wx = (const float*)d_in[20];
    const float* bx = (const float*)d_in[21];
    const float* Wh = (const float*)d_in[22];
    const float* bh = (const float*)d_in[23];
    const float* lin_a1 = (const float*)d_in[24];
    const float* lin_W  = (const float*)d_in[25];
    const float* lin_b  = (const float*)d_in[26];
    const float* lin_a2 = (const float*)d_in[27];
    float* out = (float*)d_out;

    static int attr_set = 0;
    if (!attr_set) {
        cudaFuncSetAttribute(k_xproj_mma, cudaFuncAttributeMaxDynamicSharedMemorySize, 73728);
        cudaFuncSetAttribute(k_gru_mma, cudaFuncAttributeMaxDynamicSharedMemorySize, GRU_SMEM);
        attr_set = 1;
    }

    k_zero<<<1, 256>>>();
    k_obsM<<<dim3(16, 32), 256>>>(obs_emb, obs_a_emb, obs_W);
    k_Q<<<dim3(16, 8), 256>>>(comm_emb, comm_a_emb, cw1, cw3, cw5, cw7);
    k_tok<<<32768, 128>>>(comm);
    k_obsOut<<<4096, 256>>>(obs, obs_b, obs_a, out);
    k_ypre<<<4096, 256>>>(cb1, cb3, cb5, cb7);
    k_bnfin<<<1, 256>>>(bn_g, bn_b);
    k_Wcvt2<<<768, 256>>>(Wx, 0);
    k_Wcvt2<<<768, 256>>>(Wh, 1);
    k_cvtA<<<16384, 256>>>(cnn_a);
    k_xproj_mma<<<dim3(6, 1024), 256, 73728>>>(bx);
    k_gru_mma<<<128, 256, GRU_SMEM>>>(bh);
    k_final<<<dim3(64, 4), 256>>>(lin_W, lin_b, lin_a1, lin_a2, out);
}

// round 10
// speedup vs baseline: 3.2503x; 1.1380x over previous
#include <cuda_runtime.h>
#include <cuda_fp16.h>
#include <cstdint>
#include <cstddef>

#define NTOT 4096
#define HD   256
#define LEN  32
#define KOBS 32
#define VOBS 128
#define VC   32
#define NL   131072   // NTOT*LEN

// ---------------- scratch (static device memory; no allocation) ----------------
__device__ float g_Mobs[KOBS * VOBS * HD];       // [k][v][h]   4 MB
__device__ float g_Q[16 * VC * 64];              // [tap][v][o] 128 KB
__device__ int   g_tok[NL];                      // argmax tokens
__device__ float g_ypre[(size_t)NL * HD];        // pre-BN conv output [n*l][h] 134 MB
__device__ float g_bnsum[HD];
__device__ float g_bnsq[HD];
__device__ float g_bnscale[HD];
__device__ float g_bnshift[HD];
__device__ float g_xp[(size_t)LEN * 3 * NTOT * HD]; // [l][g][n][h] 402 MB
__device__ float g_h[2][(size_t)NTOT * HD];      // GRU hidden (slot 0 = final)
__device__ unsigned short g_WxT[768 * 256];      // Wx^T fp16: [gcol][k]
__device__ unsigned short g_WhT[768 * 256];      // Wh^T fp16

__device__ __forceinline__ float prelu_f(float x, float a) { return x >= 0.f ? x : a * x; }
__device__ __forceinline__ float sigmoidf_(float x) { return 1.f / (1.f + __expf(-x)); }

__device__ __forceinline__ uint32_t smem_u32(const void* p) {
    uint32_t a;
    asm("{ .reg .u64 t; cvta.to.shared.u64 t, %1; cvt.u32.u64 %0, t; }" : "=r"(a) : "l"(p));
    return a;
}

// warp mma m16n8k16 fp16, fp32 accum (sm_80+ base feature)
__device__ __forceinline__ void mma16816(float* d, const unsigned* a, unsigned b0, unsigned b1) {
    asm volatile(
        "mma.sync.aligned.m16n8k16.row.col.f32.f16.f16.f32 "
        "{%0,%1,%2,%3}, {%4,%5,%6,%7}, {%8,%9}, {%0,%1,%2,%3};"
        : "+f"(d[0]), "+f"(d[1]), "+f"(d[2]), "+f"(d[3])
        : "r"(a[0]), "r"(a[1]), "r"(a[2]), "r"(a[3]), "r"(b0), "r"(b1));
}

#define CP_ASYNC16(dst_u32, src_ptr) \
    asm volatile("cp.async.cg.shared.global [%0], [%1], 16;" :: "r"(dst_u32), "l"(src_ptr))
#define CP_COMMIT() asm volatile("cp.async.commit_group;" ::: "memory")
#define CP_WAIT0()  asm volatile("cp.async.wait_group 0;" ::: "memory")

__device__ __forceinline__ unsigned pack_h2(float x0, float x1) {
    __half2 h = __floats2half2_rn(x0, x1);
    return *(unsigned*)&h;
}

// ---------------- zero init ----------------
__global__ void k_zero() {
    int i = threadIdx.x;
    if (i < HD) { g_bnsum[i] = 0.f; g_bnsq[i] = 0.f; }
}

// ---------------- obs lookup table ----------------
__global__ void k_obsM(const float* __restrict__ obs_emb, const float* __restrict__ aemb_p,
                       const float* __restrict__ obs_W) {
    __shared__ float P[8 * HD];
    int k = blockIdx.y;
    int vbase = blockIdx.x * 8;
    int tid = threadIdx.x;
    float a = *aemb_p;
    for (int t = tid; t < 8 * HD; t += 256)
        P[t] = prelu_f(obs_emb[vbase * HD + t], a);
    __syncthreads();

    float acc[8];
#pragma unroll
    for (int v = 0; v < 8; v++) acc[v] = 0.f;
    const float* Wp = obs_W + (size_t)k * HD * HD + tid;
    for (int i = 0; i < HD; i++) {
        float w = Wp[(size_t)i * HD];
#pragma unroll
        for (int v = 0; v < 8; v++) acc[v] += P[v * HD + i] * w;
    }
#pragma unroll
    for (int v = 0; v < 8; v++)
        g_Mobs[((size_t)k * VOBS + vbase + v) * HD + tid] = acc[v];
}

// ---------------- conv lookup tables ----------------
__global__ void k_Q(const float* __restrict__ ce, const float* __restrict__ cap,
                    const float* __restrict__ cw1, const float* __restrict__ cw3,
                    const float* __restrict__ cw5, const float* __restrict__ cw7) {
    __shared__ float Pc[HD * VC];
    int tap = blockIdx.x, tid = threadIdx.x;
    float a = *cap;
    for (int t = tid; t < VC * HD; t += 256) {
        int v = t >> 8, i = t & 255;
        Pc[i * VC + v] = prelu_f(ce[t], a);
    }
    __syncthreads();

    int g, tt;
    if (tap == 0)       { g = 0; tt = 0; }
    else if (tap < 4)   { g = 1; tt = tap - 1; }
    else if (tap < 9)   { g = 2; tt = tap - 4; }
    else                { g = 3; tt = tap - 9; }
    int ks = 2 * g + 1;
    const float* w = (g == 0) ? cw1 : (g == 1) ? cw3 : (g == 2) ? cw5 : cw7;

    int idx = blockIdx.y * 256 + tid;
    int o = idx >> 5, v = idx & 31;
    float acc = 0.f;
    for (int i = 0; i < HD; i++)
        acc += Pc[i * VC + v] * w[((size_t)o * HD + i) * ks + tt];
    g_Q[(tap * VC + v) * 64 + o] = acc;
}

// ---------------- token argmax ----------------
__global__ void k_tok(const float* __restrict__ comm) {
    int warp = (blockIdx.x * blockDim.x + threadIdx.x) >> 5;
    int lane = threadIdx.x & 31;
    if (warp >= NL) return;
    float v = comm[(size_t)warp * VC + lane];
    int idx = lane;
#pragma unroll
    for (int off = 16; off; off >>= 1) {
        float ov = __shfl_xor_sync(0xffffffffu, v, off);
        int   oi = __shfl_xor_sync(0xffffffffu, idx, off);
        if (ov > v || (ov == v && oi < idx)) { v = ov; idx = oi; }
    }
    if (lane == 0) g_tok[warp] = idx;
}

// ---------------- obs output half ----------------
__global__ void k_obsOut(const float* __restrict__ obs, const float* __restrict__ obs_b,
                         const float* __restrict__ obs_a_p, float* __restrict__ out) {
    __shared__ int sidx[KOBS];
    __shared__ int wcnt[8];
    int n = blockIdx.x, tid = threadIdx.x;
    int flag = 0;
    if (tid < VOBS) flag = obs[(size_t)n * VOBS + tid] > 0.5f;
    unsigned mask = __ballot_sync(0xffffffffu, flag);
    int lane = tid & 31, w = tid >> 5;
    if (lane == 0) wcnt[w] = __popc(mask);
    __syncthreads();
    if (flag) {
        int base = 0;
        for (int j = 0; j < w; j++) base += wcnt[j];
        sidx[base + __popc(mask & ((1u << lane) - 1u))] = tid;
    }
    __syncthreads();

    float acc = obs_b[tid];
#pragma unroll 8
    for (int k = 0; k < KOBS; k++)
        acc += g_Mobs[((size_t)k * VOBS + sidx[k]) * HD + tid];
    out[(size_t)n * (2 * HD) + tid] = prelu_f(acc, *obs_a_p);
}

// ---------------- conv-as-lookup -> y_pre + BN partial sums ----------------
__global__ void k_ypre(const float* __restrict__ cb1, const float* __restrict__ cb3,
                       const float* __restrict__ cb5, const float* __restrict__ cb7) {
    __shared__ int tk[LEN];
    int n = blockIdx.x, tid = threadIdx.x;
    if (tid < LEN) tk[tid] = g_tok[n * LEN + tid];
    __syncthreads();

    int g = tid >> 6, o = tid & 63;
    int ks = 2 * g + 1, pad = g, base = g * g;
    const float* cbp = (g == 0) ? cb1 : (g == 1) ? cb3 : (g == 2) ? cb5 : cb7;
    float bias = cbp[o];

    float ls = 0.f, lq = 0.f;
    for (int l = 0; l < LEN; l++) {
        float acc = bias;
        for (int t = 0; t < ks; t++) {
            int lp = l + t - pad;
            if (lp >= 0 && lp < LEN)
                acc += g_Q[((base + t) * VC + tk[lp]) * 64 + o];
        }
        g_ypre[((size_t)n * LEN + l) * HD + tid] = acc;
        ls += acc; lq += acc * acc;
    }
    atomicAdd(&g_bnsum[tid], ls);
    atomicAdd(&g_bnsq[tid], lq);
}

// ---------------- BN finalize ----------------
__global__ void k_bnfin(const float* __restrict__ bn_g, const float* __restrict__ bn_b) {
    int h = threadIdx.x;
    float m   = g_bnsum[h] * (1.0f / 131072.0f);
    float var = g_bnsq[h]  * (1.0f / 131072.0f) - m * m;
    float sc  = bn_g[h] * rsqrtf(var + 1e-5f);
    g_bnscale[h] = sc;
    g_bnshift[h] = bn_b[h] - m * sc;
}

// ---------------- weight transpose -> fp16: W[3][256][256] (g,k,n) -> [gcol][k] ----------------
__global__ void k_Wcvt2(const float* __restrict__ W, int sel) {
    int j = blockIdx.x;      // gcol 0..767 (= g*256 + n)
    int k = threadIdx.x;     // 0..255
    float v = W[(size_t)(j >> 8) * 65536 + (size_t)k * 256 + (j & 255)];
    __half h = __float2half_rn(v);
    unsigned short* dst = sel ? g_WhT : g_WxT;
    dst[j * 256 + k] = *(unsigned short*)&h;
}

// ---------------- xproj via fp16 mma.sync: [131072,256] x [256,768], tiles 128x128 ----------------
// grid (6, 1024): x = coltile (fast -> A row-tile L2 reuse). A converted inline (BN+prelu+fp16).
__global__ void __launch_bounds__(256) k_xproj_mma(const float* __restrict__ bx,
                                                   const float* __restrict__ cnn_a_p) {
    __shared__ __align__(16) unsigned short Ah[128 * 72];
    __shared__ __align__(16) unsigned short Bh[128 * 72];
    __shared__ float sSc[HD], sSh[HD];
    int tid = threadIdx.x, wid = tid >> 5, lane = tid & 31;
    int tg = lane >> 2, tiG = lane & 3;
    int warp_m = wid >> 1, warp_n = wid & 1;
    int rowbase = blockIdx.y * 128, colbase = blockIdx.x * 128;
    int gsel = colbase >> 8;
    float ca = *cnn_a_p;

    if (tid < HD) { sSc[tid] = g_bnscale[tid]; sSh[tid] = g_bnshift[tid]; }

    float acc[2][8][4];
#pragma unroll
    for (int mt = 0; mt < 2; mt++)
#pragma unroll
        for (int nt = 0; nt < 8; nt++)
#pragma unroll
            for (int u = 0; u < 4; u++) acc[mt][nt][u] = 0.f;

    for (int kc = 0; kc < 4; kc++) {
        __syncthreads();
        for (int i = tid; i < 1024; i += 256) {
            int r = i >> 3, q = i & 7;
            int k0 = kc * 64 + q * 8;
            // A: load fp32, BN+prelu, convert fp16
            const float* src = &g_ypre[(size_t)(rowbase + r) * HD + k0];
            float4 v0 = *(const float4*)src;
            float4 v1 = *(const float4*)(src + 4);
            float v[8] = {v0.x, v0.y, v0.z, v0.w, v1.x, v1.y, v1.z, v1.w};
            unsigned pk[4];
#pragma unroll
            for (int e = 0; e < 4; e++) {
                int ch = k0 + 2 * e;
                float x0 = prelu_f(v[2*e]   * sSc[ch]   + sSh[ch],   ca);
                float x1 = prelu_f(v[2*e+1] * sSc[ch+1] + sSh[ch+1], ca);
                pk[e] = pack_h2(x0, x1);
            }
            *(uint4*)&Ah[r * 72 + q * 8] = make_uint4(pk[0], pk[1], pk[2], pk[3]);
            // B: direct fp16 copy
            *(uint4*)&Bh[r * 72 + q * 8] =
                *(const uint4*)&g_WxT[(size_t)(colbase + r) * 256 + k0];
        }
        __syncthreads();
#pragma unroll
        for (int ks = 0; ks < 4; ks++) {
            int k0 = ks * 16;
            unsigned ah[2][4];
#pragma unroll
            for (int mt = 0; mt < 2; mt++) {
                int r = warp_m * 32 + mt * 16 + tg;
                ah[mt][0] = *(const unsigned*)&Ah[r * 72 + k0 + 2 * tiG];
                ah[mt][1] = *(const unsigned*)&Ah[(r + 8) * 72 + k0 + 2 * tiG];
                ah[mt][2] = *(const unsigned*)&Ah[r * 72 + k0 + 8 + 2 * tiG];
                ah[mt][3] = *(const unsigned*)&Ah[(r + 8) * 72 + k0 + 8 + 2 * tiG];
            }
#pragma unroll
            for (int nt = 0; nt < 8; nt++) {
                int c = warp_n * 64 + nt * 8 + tg;
                unsigned b0 = *(const unsigned*)&Bh[c * 72 + k0 + 2 * tiG];
                unsigned b1 = *(const unsigned*)&Bh[c * 72 + k0 + 8 + 2 * tiG];
#pragma unroll
                for (int mt = 0; mt < 2; mt++)
                    mma16816(acc[mt][nt], ah[mt], b0, b1);
            }
        }
    }

    // epilogue: add bias, scatter to g_xp[l][g][n][h]
#pragma unroll
    for (int mt = 0; mt < 2; mt++) {
#pragma unroll
        for (int nt = 0; nt < 8; nt++) {
            int cg = colbase + warp_n * 64 + nt * 8 + 2 * tiG;
            int hcol = cg & 255;
            float bx0 = bx[gsel * 256 + hcol], bx1 = bx[gsel * 256 + hcol + 1];
            int r0 = rowbase + warp_m * 32 + mt * 16 + tg;
            int r1 = r0 + 8;
            int n0 = r0 >> 5, l0 = r0 & 31;
            int n1 = r1 >> 5, l1 = r1 & 31;
            float2 o0 = make_float2(acc[mt][nt][0] + bx0, acc[mt][nt][1] + bx1);
            float2 o1 = make_float2(acc[mt][nt][2] + bx0, acc[mt][nt][3] + bx1);
            *(float2*)&g_xp[(((size_t)l0 * 3 + gsel) * NTOT + n0) * HD + hcol] = o0;
            *(float2*)&g_xp[(((size_t)l1 * 3 + gsel) * NTOT + n1) * HD + hcol] = o1;
        }
    }
}

// ---------------- persistent GRU via fp16 mma.sync + cp.async double-buffered B ----------------
// smem: h float[32][258] (33024B) | Ah ushort[32][264] (16896B)
//       | 2 stage bufs, each Bh ushort[192][72] (27648B)
#define GRU_H_BYTES   33024
#define GRU_A_BYTES   16896
#define GRU_STG_BYTES 27648
#define GRU_SMEM (GRU_H_BYTES + GRU_A_BYTES + 2 * GRU_STG_BYTES)   // 105216
__global__ void __launch_bounds__(256) k_gru_mma(const float* __restrict__ bh) {
    extern __shared__ __align__(16) char gsm[];
    float* hsh = (float*)gsm;
    unsigned short* Ah = (unsigned short*)(gsm + GRU_H_BYTES);
    char* bstage = gsm + GRU_H_BYTES + GRU_A_BYTES;
    int tid = threadIdx.x, wid = tid >> 5, lane = tid & 31;
    int tg = lane >> 2, tiG = lane & 3;
    int warp_m = wid >> 2, warp_n = wid & 3;
    int base = blockIdx.x * 32;

    for (int i = tid; i < 32 * 258; i += 256) hsh[i] = 0.f;

    for (int step = 0; step < LEN; step++) {
        __syncthreads();   // prior-step h writes visible; stage bufs free

        // issue stage 0 load (overlaps with h conversion)
        for (int i = tid; i < 1536; i += 256) {
            int r = i >> 3, q = i & 7;
            int gcol = (r >> 6) * 256 + (r & 63);     // nc=0, kc=0
            CP_ASYNC16(smem_u32(bstage + r * 144 + q * 16),
                       &g_WhT[(size_t)gcol * 256 + q * 8]);
        }
        CP_COMMIT();

        // h -> fp16
        for (int i = tid; i < 4096; i += 256) {
            int r = i >> 7, cp = i & 127;
            float2 v = *(const float2*)&hsh[r * 258 + cp * 2];
            *(unsigned*)&Ah[r * 264 + cp * 2] = pack_h2(v.x, v.y);
        }
        __syncthreads();   // A ready

        for (int nc = 0; nc < 4; nc++) {
            float acc[3][2][4];
#pragma unroll
            for (int g = 0; g < 3; g++)
#pragma unroll
                for (int nt = 0; nt < 2; nt++)
#pragma unroll
                    for (int u = 0; u < 4; u++) acc[g][nt][u] = 0.f;

            // prefetch x-gate values for this col chunk (hidden under mma)
            float2 xr[2][2], xz[2][2], xn[2][2], ho[2][2];
#pragma unroll
            for (int nt = 0; nt < 2; nt++) {
                int ccol = nc * 64 + warp_n * 16 + nt * 8 + 2 * tiG;
#pragma unroll
                for (int half = 0; half < 2; half++) {
                    int r = warp_m * 16 + tg + half * 8;
                    size_t xb = (((size_t)step * 3) * NTOT + base + r) * HD + ccol;
                    xr[nt][half] = *(const float2*)&g_xp[xb];
                    xz[nt][half] = *(const float2*)&g_xp[xb + (size_t)NTOT * HD];
                    xn[nt][half] = *(const float2*)&g_xp[xb + 2 * (size_t)NTOT * HD];
                    ho[nt][half] = *(const float2*)&hsh[r * 258 + ccol];
                }
            }

            for (int kc = 0; kc < 4; kc++) {
                int s = nc * 4 + kc;
                CP_WAIT0();        // stage s arrived
                __syncthreads();   // all warps done with stage s-1 buffer
                if (s < 15) {      // prefetch stage s+1
                    int s1 = s + 1;
                    int nc_ = s1 >> 2, kc_ = s1 & 3;
                    char* dst = bstage + (s1 & 1) * GRU_STG_BYTES;
                    for (int i = tid; i < 1536; i += 256) {
                        int r = i >> 3, q = i & 7;
                        int gcol = (r >> 6) * 256 + nc_ * 64 + (r & 63);
                        CP_ASYNC16(smem_u32(dst + r * 144 + q * 16),
                                   &g_WhT[(size_t)gcol * 256 + kc_ * 64 + q * 8]);
                    }
                    CP_COMMIT();
                }

                unsigned short* Bh = (unsigned short*)(bstage + (s & 1) * GRU_STG_BYTES);
#pragma unroll
                for (int ks = 0; ks < 4; ks++) {
                    int kA = kc * 64 + ks * 16;
                    int kB = ks * 16;
                    unsigned ah[4];
                    int r = warp_m * 16 + tg;
                    ah[0] = *(const unsigned*)&Ah[r * 264 + kA + 2 * tiG];
                    ah[1] = *(const unsigned*)&Ah[(r + 8) * 264 + kA + 2 * tiG];
                    ah[2] = *(const unsigned*)&Ah[r * 264 + kA + 8 + 2 * tiG];
                    ah[3] = *(const unsigned*)&Ah[(r + 8) * 264 + kA + 8 + 2 * tiG];
#pragma unroll
                    for (int g = 0; g < 3; g++) {
#pragma unroll
                        for (int nt = 0; nt < 2; nt++) {
                            int br = g * 64 + warp_n * 16 + nt * 8 + tg;
                            unsigned b0 = *(const unsigned*)&Bh[br * 72 + kB + 2 * tiG];
                            unsigned b1 = *(const unsigned*)&Bh[br * 72 + kB + 8 + 2 * tiG];
                            mma16816(acc[g][nt], ah, b0, b1);
                        }
                    }
                }
            }

            // gate math for this col chunk
#pragma unroll
            for (int nt = 0; nt < 2; nt++) {
                int ccol = nc * 64 + warp_n * 16 + nt * 8 + 2 * tiG;
                float2 br2 = *(const float2*)&bh[ccol];
                float2 bz2 = *(const float2*)&bh[256 + ccol];
                float2 bn2 = *(const float2*)&bh[512 + ccol];
#pragma unroll
                for (int half = 0; half < 2; half++) {
                    int r = warp_m * 16 + tg + half * 8;
                    int ai = half * 2;
                    float rr0 = sigmoidf_(xr[nt][half].x + acc[0][nt][ai]     + br2.x);
                    float rr1 = sigmoidf_(xr[nt][half].y + acc[0][nt][ai + 1] + br2.y);
                    float zz0 = sigmoidf_(xz[nt][half].x + acc[1][nt][ai]     + bz2.x);
                    float zz1 = sigmoidf_(xz[nt][half].y + acc[1][nt][ai + 1] + bz2.y);
                    float nn0 = tanhf(xn[nt][half].x + rr0 * (acc[2][nt][ai]     + bn2.x));
                    float nn1 = tanhf(xn[nt][half].y + rr1 * (acc[2][nt][ai + 1] + bn2.y));
                    float2 hn;
                    hn.x = nn0 * (1.f - zz0) + ho[nt][half].x * zz0;
                    hn.y = nn1 * (1.f - zz1) + ho[nt][half].y * zz1;
                    *(float2*)&hsh[r * 258 + ccol] = hn;
                }
            }
        }
    }
    __syncthreads();
    for (int i = tid; i < 32 * HD; i += 256) {
        int r = i >> 8, c = i & 255;
        g_h[0][(size_t)(base + r) * HD + c] = hsh[r * 258 + c];
    }
}

// ---------------- final linear ----------------
__global__ void k_final(const float* __restrict__ linW, const float* __restrict__ linb,
                        const float* __restrict__ a1p, const float* __restrict__ a2p,
                        float* __restrict__ out) {
    __shared__ __align__(16) float As[64][33];
    __shared__ __align__(16) float Bs[32][64];
    float a1 = *a1p, a2 = *a2p;
    int tid = threadIdx.x;
    int rowbase = blockIdx.x * 64, cbase = blockIdx.y * 64;
    int tx = tid & 15, ty = tid >> 4;

    float acc[4][4];
#pragma unroll
    for (int j = 0; j < 4; j++)
#pragma unroll
        for (int u = 0; u < 4; u++) acc[j][u] = 0.f;

    for (int i0 = 0; i0 < HD; i0 += 32) {
        for (int t = tid; t < 64 * 32; t += 256) {
            int kk = t & 31, r = t >> 5;
            As[r][kk] = prelu_f(g_h[0][(size_t)(rowbase + r) * HD + i0 + kk], a1);
        }
        for (int t = tid; t < 32 * 64; t += 256) {
            int c = t & 63, kk = t >> 6;
            Bs[kk][c] = linW[(size_t)(i0 + kk) * HD + cbase + c];
        }
        __syncthreads();
#pragma unroll
        for (int kk = 0; kk < 32; kk++) {
            float a[4];
#pragma unroll
            for (int j = 0; j < 4; j++) a[j] = As[ty * 4 + j][kk];
            float4 b = *(const float4*)&Bs[kk][tx * 4];
#pragma unroll
            for (int j = 0; j < 4; j++) {
                acc[j][0] += a[j] * b.x; acc[j][1] += a[j] * b.y;
                acc[j][2] += a[j] * b.z; acc[j][3] += a[j] * b.w;
            }
        }
        __syncthreads();
    }
#pragma unroll
    for (int j = 0; j < 4; j++) {
        int row = rowbase + ty * 4 + j;
#pragma unroll
        for (int u = 0; u < 4; u++) {
            int c = cbase + tx * 4 + u;
            out[(size_t)row * 512 + 256 + c] = prelu_f(acc[j][u] + linb[c], a2);
        }
    }
}

// ---------------- launch ----------------
extern "C" void kernel_launch(void* const* d_in, const int* in_sizes, int n_in,
                              void* d_out, int out_size) {
    (void)in_sizes; (void)n_in; (void)out_size;
    const float* obs        = (const float*)d_in[0];
    const float* comm       = (const float*)d_in[1];
    const float* obs_emb    = (const float*)d_in[2];
    const float* obs_a_emb  = (const float*)d_in[3];
    const float* obs_W      = (const float*)d_in[4];
    const float* obs_b      = (const float*)d_in[5];
    const float* obs_a      = (const float*)d_in[6];
    const float* comm_emb   = (const float*)d_in[7];
    const float* comm_a_emb = (const float*)d_in[8];
    const float* cw1 = (const float*)d_in[9];
    const float* cb1 = (const float*)d_in[10];
    const float* cw3 = (const float*)d_in[11];
    const float* cb3 = (const float*)d_in[12];
    const float* cw5 = (const float*)d_in[13];
    const float* cb5 = (const float*)d_in[14];
    const float* cw7 = (const float*)d_in[15];
    const float* cb7 = (const float*)d_in[16];
    const float* bn_g  = (const float*)d_in[17];
    const float* bn_b  = (const float*)d_in[18];
    const float* cnn_a = (const float*)d_in[19];
    const float* Wx = (const float*)d_in[20];
    const float* bx = (const float*)d_in[21];
    const float* Wh = (const float*)d_in[22];
    const float* bh = (const float*)d_in[23];
    const float* lin_a1 = (const float*)d_in[24];
    const float* lin_W  = (const float*)d_in[25];
    const float* lin_b  = (const float*)d_in[26];
    const float* lin_a2 = (const float*)d_in[27];
    float* out = (float*)d_out;

    static int attr_set = 0;
    if (!attr_set) {
        cudaFuncSetAttribute(k_gru_mma, cudaFuncAttributeMaxDynamicSharedMemorySize, GRU_SMEM);
        attr_set = 1;
    }

    k_zero<<<1, 256>>>();
    k_obsM<<<dim3(16, 32), 256>>>(obs_emb, obs_a_emb, obs_W);
    k_Q<<<dim3(16, 8), 256>>>(comm_emb, comm_a_emb, cw1, cw3, cw5, cw7);
    k_tok<<<32768, 128>>>(comm);
    k_obsOut<<<4096, 256>>>(obs, obs_b, obs_a, out);
    k_ypre<<<4096, 256>>>(cb1, cb3, cb5, cb7);
    k_bnfin<<<1, 256>>>(bn_g, bn_b);
    k_Wcvt2<<<768, 256>>>(Wx, 0);
    k_Wcvt2<<<768, 256>>>(Wh, 1);
    k_xproj_mma<<<dim3(6, 1024), 256>>>(bx, cnn_a);
    k_gru_mma<<<128, 256, GRU_SMEM>>>(bh);
    k_final<<<dim3(64, 4), 256>>>(lin_W, lin_b, lin_a1, lin_a2, out);
}

// round 13
// speedup vs baseline: 3.4175x; 1.0515x over previous
#include <cuda_runtime.h>
#include <cuda_fp16.h>
#include <cstdint>
#include <cstddef>

#define NTOT 4096
#define HD   256
#define LEN  32
#define KOBS 32
#define VOBS 128
#define VC   32
#define NL   131072   // NTOT*LEN

// ---------------- scratch (static device memory; no allocation) ----------------
__device__ float g_Mobs[KOBS * VOBS * HD];       // [k][v][h]   4 MB
__device__ float g_Q[16 * VC * 64];              // [tap][v][o] 128 KB
__device__ int   g_tok[NL];                      // argmax tokens
__device__ float g_ypre[(size_t)NL * HD];        // pre-BN conv output [n*l][h] 134 MB
__device__ float g_bnsum[HD];
__device__ float g_bnsq[HD];
__device__ float g_bnscale[HD];
__device__ float g_bnshift[HD];
__device__ unsigned short g_xph[(size_t)LEN * 3 * NTOT * HD]; // [l][g][n][h] fp16 bits, 201 MB
__device__ float g_h[2][(size_t)NTOT * HD];      // GRU hidden (slot 0 = final)
__device__ unsigned short g_WxT[768 * 256];      // Wx^T fp16: [gcol][k]
__device__ unsigned short g_WhT[768 * 256];      // Wh^T fp16

__device__ __forceinline__ float prelu_f(float x, float a) { return x >= 0.f ? x : a * x; }
__device__ __forceinline__ float sigmoidf_(float x) { return 1.f / (1.f + __expf(-x)); }

__device__ __forceinline__ uint32_t smem_u32(const void* p) {
    uint32_t a;
    asm("{ .reg .u64 t; cvta.to.shared.u64 t, %1; cvt.u32.u64 %0, t; }" : "=r"(a) : "l"(p));
    return a;
}

// warp mma m16n8k16 fp16, fp32 accum (sm_80+ base feature)
__device__ __forceinline__ void mma16816(float* d, const unsigned* a, unsigned b0, unsigned b1) {
    asm volatile(
        "mma.sync.aligned.m16n8k16.row.col.f32.f16.f16.f32 "
        "{%0,%1,%2,%3}, {%4,%5,%6,%7}, {%8,%9}, {%0,%1,%2,%3};"
        : "+f"(d[0]), "+f"(d[1]), "+f"(d[2]), "+f"(d[3])
        : "r"(a[0]), "r"(a[1]), "r"(a[2]), "r"(a[3]), "r"(b0), "r"(b1));
}

#define CP_ASYNC16(dst_u32, src_ptr) \
    asm volatile("cp.async.cg.shared.global [%0], [%1], 16;" :: "r"(dst_u32), "l"(src_ptr))
#define CP_COMMIT() asm volatile("cp.async.commit_group;" ::: "memory")
#define CP_WAIT0()  asm volatile("cp.async.wait_group 0;" ::: "memory")

__device__ __forceinline__ unsigned pack_h2(float x0, float x1) {
    __half2 h = __floats2half2_rn(x0, x1);
    return *(unsigned*)&h;
}
__device__ __forceinline__ float2 unpack_h2(unsigned u) {
    __half2 h = *(__half2*)&u;
    return __half22float2(h);
}

// ---------------- zero init ----------------
__global__ void k_zero() {
    int i = threadIdx.x;
    if (i < HD) { g_bnsum[i] = 0.f; g_bnsq[i] = 0.f; }
}

// ---------------- obs lookup table ----------------
__global__ void k_obsM(const float* __restrict__ obs_emb, const float* __restrict__ aemb_p,
                       const float* __restrict__ obs_W) {
    __shared__ float P[8 * HD];
    int k = blockIdx.y;
    int vbase = blockIdx.x * 8;
    int tid = threadIdx.x;
    float a = *aemb_p;
    for (int t = tid; t < 8 * HD; t += 256)
        P[t] = prelu_f(obs_emb[vbase * HD + t], a);
    __syncthreads();

    float acc[8];
#pragma unroll
    for (int v = 0; v < 8; v++) acc[v] = 0.f;
    const float* Wp = obs_W + (size_t)k * HD * HD + tid;
    for (int i = 0; i < HD; i++) {
        float w = Wp[(size_t)i * HD];
#pragma unroll
        for (int v = 0; v < 8; v++) acc[v] += P[v * HD + i] * w;
    }
#pragma unroll
    for (int v = 0; v < 8; v++)
        g_Mobs[((size_t)k * VOBS + vbase + v) * HD + tid] = acc[v];
}

// ---------------- conv lookup tables ----------------
__global__ void k_Q(const float* __restrict__ ce, const float* __restrict__ cap,
                    const float* __restrict__ cw1, const float* __restrict__ cw3,
                    const float* __restrict__ cw5, const float* __restrict__ cw7) {
    __shared__ float Pc[HD * VC];
    int tap = blockIdx.x, tid = threadIdx.x;
    float a = *cap;
    for (int t = tid; t < VC * HD; t += 256) {
        int v = t >> 8, i = t & 255;
        Pc[i * VC + v] = prelu_f(ce[t], a);
    }
    __syncthreads();

    int g, tt;
    if (tap == 0)       { g = 0; tt = 0; }
    else if (tap < 4)   { g = 1; tt = tap - 1; }
    else if (tap < 9)   { g = 2; tt = tap - 4; }
    else                { g = 3; tt = tap - 9; }
    int ks = 2 * g + 1;
    const float* w = (g == 0) ? cw1 : (g == 1) ? cw3 : (g == 2) ? cw5 : cw7;

    int idx = blockIdx.y * 256 + tid;
    int o = idx >> 5, v = idx & 31;
    float acc = 0.f;
    for (int i = 0; i < HD; i++)
        acc += Pc[i * VC + v] * w[((size_t)o * HD + i) * ks + tt];
    g_Q[(tap * VC + v) * 64 + o] = acc;
}

// ---------------- token argmax ----------------
__global__ void k_tok(const float* __restrict__ comm) {
    int warp = (blockIdx.x * blockDim.x + threadIdx.x) >> 5;
    int lane = threadIdx.x & 31;
    if (warp >= NL) return;
    float v = comm[(size_t)warp * VC + lane];
    int idx = lane;
#pragma unroll
    for (int off = 16; off; off >>= 1) {
        float ov = __shfl_xor_sync(0xffffffffu, v, off);
        int   oi = __shfl_xor_sync(0xffffffffu, idx, off);
        if (ov > v || (ov == v && oi < idx)) { v = ov; idx = oi; }
    }
    if (lane == 0) g_tok[warp] = idx;
}

// ---------------- obs output half ----------------
__global__ void k_obsOut(const float* __restrict__ obs, const float* __restrict__ obs_b,
                         const float* __restrict__ obs_a_p, float* __restrict__ out) {
    __shared__ int sidx[KOBS];
    __shared__ int wcnt[8];
    int n = blockIdx.x, tid = threadIdx.x;
    int flag = 0;
    if (tid < VOBS) flag = obs[(size_t)n * VOBS + tid] > 0.5f;
    unsigned mask = __ballot_sync(0xffffffffu, flag);
    int lane = tid & 31, w = tid >> 5;
    if (lane == 0) wcnt[w] = __popc(mask);
    __syncthreads();
    if (flag) {
        int base = 0;
        for (int j = 0; j < w; j++) base += wcnt[j];
        sidx[base + __popc(mask & ((1u << lane) - 1u))] = tid;
    }
    __syncthreads();

    float acc = obs_b[tid];
#pragma unroll 8
    for (int k = 0; k < KOBS; k++)
        acc += g_Mobs[((size_t)k * VOBS + sidx[k]) * HD + tid];
    out[(size_t)n * (2 * HD) + tid] = prelu_f(acc, *obs_a_p);
}

// ---------------- conv-as-lookup -> y_pre + BN partial sums ----------------
__global__ void k_ypre(const float* __restrict__ cb1, const float* __restrict__ cb3,
                       const float* __restrict__ cb5, const float* __restrict__ cb7) {
    __shared__ int tk[LEN];
    int n = blockIdx.x, tid = threadIdx.x;
    if (tid < LEN) tk[tid] = g_tok[n * LEN + tid];
    __syncthreads();

    int g = tid >> 6, o = tid & 63;
    int ks = 2 * g + 1, pad = g, base = g * g;
    const float* cbp = (g == 0) ? cb1 : (g == 1) ? cb3 : (g == 2) ? cb5 : cb7;
    float bias = cbp[o];

    float ls = 0.f, lq = 0.f;
    for (int l = 0; l < LEN; l++) {
        float acc = bias;
        for (int t = 0; t < ks; t++) {
            int lp = l + t - pad;
            if (lp >= 0 && lp < LEN)
                acc += g_Q[((base + t) * VC + tk[lp]) * 64 + o];
        }
        g_ypre[((size_t)n * LEN + l) * HD + tid] = acc;
        ls += acc; lq += acc * acc;
    }
    atomicAdd(&g_bnsum[tid], ls);
    atomicAdd(&g_bnsq[tid], lq);
}

// ---------------- BN finalize ----------------
__global__ void k_bnfin(const float* __restrict__ bn_g, const float* __restrict__ bn_b) {
    int h = threadIdx.x;
    float m   = g_bnsum[h] * (1.0f / 131072.0f);
    float var = g_bnsq[h]  * (1.0f / 131072.0f) - m * m;
    float sc  = bn_g[h] * rsqrtf(var + 1e-5f);
    g_bnscale[h] = sc;
    g_bnshift[h] = bn_b[h] - m * sc;
}

// ---------------- weight transpose -> fp16: W[3][256][256] (g,k,n) -> [gcol][k] ----------------
__global__ void k_Wcvt2(const float* __restrict__ W, int sel) {
    int j = blockIdx.x;      // gcol 0..767 (= g*256 + n)
    int k = threadIdx.x;     // 0..255
    float v = W[(size_t)(j >> 8) * 65536 + (size_t)k * 256 + (j & 255)];
    __half h = __float2half_rn(v);
    unsigned short* dst = sel ? g_WhT : g_WxT;
    dst[j * 256 + k] = *(unsigned short*)&h;
}

// ---------------- xproj via fp16 mma.sync: [131072,256] x [256,768], tiles 128x128 ----------------
// grid (6, 1024): x = coltile (fast -> A row-tile L2 reuse). A converted inline (BN+prelu+fp16).
__global__ void __launch_bounds__(256) k_xproj_mma(const float* __restrict__ bx,
                                                   const float* __restrict__ cnn_a_p) {
    __shared__ __align__(16) unsigned short Ah[128 * 72];
    __shared__ __align__(16) unsigned short Bh[128 * 72];
    __shared__ float sSc[HD], sSh[HD];
    int tid = threadIdx.x, wid = tid >> 5, lane = tid & 31;
    int tg = lane >> 2, tiG = lane & 3;
    int warp_m = wid >> 1, warp_n = wid & 1;
    int rowbase = blockIdx.y * 128, colbase = blockIdx.x * 128;
    int gsel = colbase >> 8;
    float ca = *cnn_a_p;

    if (tid < HD) { sSc[tid] = g_bnscale[tid]; sSh[tid] = g_bnshift[tid]; }

    float acc[2][8][4];
#pragma unroll
    for (int mt = 0; mt < 2; mt++)
#pragma unroll
        for (int nt = 0; nt < 8; nt++)
#pragma unroll
            for (int u = 0; u < 4; u++) acc[mt][nt][u] = 0.f;

    for (int kc = 0; kc < 4; kc++) {
        __syncthreads();
        for (int i = tid; i < 1024; i += 256) {
            int r = i >> 3, q = i & 7;
            int k0 = kc * 64 + q * 8;
            const float* src = &g_ypre[(size_t)(rowbase + r) * HD + k0];
            float4 v0 = *(const float4*)src;
            float4 v1 = *(const float4*)(src + 4);
            float v[8] = {v0.x, v0.y, v0.z, v0.w, v1.x, v1.y, v1.z, v1.w};
            unsigned pk[4];
#pragma unroll
            for (int e = 0; e < 4; e++) {
                int ch = k0 + 2 * e;
                float x0 = prelu_f(v[2*e]   * sSc[ch]   + sSh[ch],   ca);
                float x1 = prelu_f(v[2*e+1] * sSc[ch+1] + sSh[ch+1], ca);
                pk[e] = pack_h2(x0, x1);
            }
            *(uint4*)&Ah[r * 72 + q * 8] = make_uint4(pk[0], pk[1], pk[2], pk[3]);
            *(uint4*)&Bh[r * 72 + q * 8] =
                *(const uint4*)&g_WxT[(size_t)(colbase + r) * 256 + k0];
        }
        __syncthreads();
#pragma unroll
        for (int ks = 0; ks < 4; ks++) {
            int k0 = ks * 16;
            unsigned ah[2][4];
#pragma unroll
            for (int mt = 0; mt < 2; mt++) {
                int r = warp_m * 32 + mt * 16 + tg;
                ah[mt][0] = *(const unsigned*)&Ah[r * 72 + k0 + 2 * tiG];
                ah[mt][1] = *(const unsigned*)&Ah[(r + 8) * 72 + k0 + 2 * tiG];
                ah[mt][2] = *(const unsigned*)&Ah[r * 72 + k0 + 8 + 2 * tiG];
                ah[mt][3] = *(const unsigned*)&Ah[(r + 8) * 72 + k0 + 8 + 2 * tiG];
            }
#pragma unroll
            for (int nt = 0; nt < 8; nt++) {
                int c = warp_n * 64 + nt * 8 + tg;
                unsigned b0 = *(const unsigned*)&Bh[c * 72 + k0 + 2 * tiG];
                unsigned b1 = *(const unsigned*)&Bh[c * 72 + k0 + 8 + 2 * tiG];
#pragma unroll
                for (int mt = 0; mt < 2; mt++)
                    mma16816(acc[mt][nt], ah[mt], b0, b1);
            }
        }
    }

    // epilogue: add bias, convert fp16, scatter to g_xph[l][g][n][h]
#pragma unroll
    for (int mt = 0; mt < 2; mt++) {
#pragma unroll
        for (int nt = 0; nt < 8; nt++) {
            int cg = colbase + warp_n * 64 + nt * 8 + 2 * tiG;
            int hcol = cg & 255;
            float bx0 = bx[gsel * 256 + hcol], bx1 = bx[gsel * 256 + hcol + 1];
            int r0 = rowbase + warp_m * 32 + mt * 16 + tg;
            int r1 = r0 + 8;
            int n0 = r0 >> 5, l0 = r0 & 31;
            int n1 = r1 >> 5, l1 = r1 & 31;
            unsigned o0 = pack_h2(acc[mt][nt][0] + bx0, acc[mt][nt][1] + bx1);
            unsigned o1 = pack_h2(acc[mt][nt][2] + bx0, acc[mt][nt][3] + bx1);
            *(unsigned*)&g_xph[(((size_t)l0 * 3 + gsel) * NTOT + n0) * HD + hcol] = o0;
            *(unsigned*)&g_xph[(((size_t)l1 * 3 + gsel) * NTOT + n1) * HD + hcol] = o1;
        }
    }
}

// ---------------- persistent GRU via fp16 mma.sync, 512 threads (16 warps) ----------------
// smem: h float[32][258] (33024B) | Ah ushort[32][264] (16896B)
//       | 2 stage bufs, each Bh ushort[192][72] (27648B)
#define GRU_H_BYTES   33024
#define GRU_A_BYTES   16896
#define GRU_STG_BYTES 27648
#define GRU_SMEM (GRU_H_BYTES + GRU_A_BYTES + 2 * GRU_STG_BYTES)   // 105216
#define GRU_THREADS 512
__global__ void __launch_bounds__(GRU_THREADS) k_gru_mma(const float* __restrict__ bh) {
    extern __shared__ __align__(16) char gsm[];
    float* hsh = (float*)gsm;
    unsigned short* Ah = (unsigned short*)(gsm + GRU_H_BYTES);
    char* bstage = gsm + GRU_H_BYTES + GRU_A_BYTES;
    int tid = threadIdx.x, wid = tid >> 5, lane = tid & 31;
    int tg = lane >> 2, tiG = lane & 3;
    int warp_m = wid >> 3;        // 0..1 : rows warp_m*16 .. +15
    int warp_n = wid & 7;         // 0..7 : col sub-tile (8 cols per gate chunk)
    int base = blockIdx.x * 32;

    for (int i = tid; i < 32 * 258; i += GRU_THREADS) hsh[i] = 0.f;

    for (int step = 0; step < LEN; step++) {
        __syncthreads();   // prior-step h writes visible; stage bufs free

        // issue stage 0 load (overlaps with h conversion)
        for (int i = tid; i < 1536; i += GRU_THREADS) {
            int r = i >> 3, q = i & 7;
            int gcol = (r >> 6) * 256 + (r & 63);     // nc=0, kc=0
            CP_ASYNC16(smem_u32(bstage + r * 144 + q * 16),
                       &g_WhT[(size_t)gcol * 256 + q * 8]);
        }
        CP_COMMIT();

        // h -> fp16
        for (int i = tid; i < 4096; i += GRU_THREADS) {
            int r = i >> 7, cp = i & 127;
            float2 v = *(const float2*)&hsh[r * 258 + cp * 2];
            *(unsigned*)&Ah[r * 264 + cp * 2] = pack_h2(v.x, v.y);
        }
        __syncthreads();   // A ready

        for (int nc = 0; nc < 4; nc++) {
            float acc[3][4];
#pragma unroll
            for (int g = 0; g < 3; g++)
#pragma unroll
                for (int u = 0; u < 4; u++) acc[g][u] = 0.f;

            // prefetch x-gate values (fp16) + old h for this col chunk
            int ccol = nc * 64 + warp_n * 8 + 2 * tiG;
            float2 xr[2], xz[2], xn[2], ho[2];
#pragma unroll
            for (int half = 0; half < 2; half++) {
                int r = warp_m * 16 + tg + half * 8;
                size_t xb = (((size_t)step * 3) * NTOT + base + r) * HD + ccol;
                xr[half] = unpack_h2(*(const unsigned*)&g_xph[xb]);
                xz[half] = unpack_h2(*(const unsigned*)&g_xph[xb + (size_t)NTOT * HD]);
                xn[half] = unpack_h2(*(const unsigned*)&g_xph[xb + 2 * (size_t)NTOT * HD]);
                ho[half] = *(const float2*)&hsh[r * 258 + ccol];
            }

            for (int kc = 0; kc < 4; kc++) {
                int s = nc * 4 + kc;
                CP_WAIT0();        // stage s arrived
                __syncthreads();   // all warps done with stage s-1 buffer
                if (s < 15) {      // prefetch stage s+1
                    int s1 = s + 1;
                    int nc_ = s1 >> 2, kc_ = s1 & 3;
                    char* dst = bstage + (s1 & 1) * GRU_STG_BYTES;
                    for (int i = tid; i < 1536; i += GRU_THREADS) {
                        int r = i >> 3, q = i & 7;
                        int gcol = (r >> 6) * 256 + nc_ * 64 + (r & 63);
                        CP_ASYNC16(smem_u32(dst + r * 144 + q * 16),
                                   &g_WhT[(size_t)gcol * 256 + kc_ * 64 + q * 8]);
                    }
                    CP_COMMIT();
                }

                unsigned short* Bh = (unsigned short*)(bstage + (s & 1) * GRU_STG_BYTES);
#pragma unroll
                for (int ks = 0; ks < 4; ks++) {
                    int kA = kc * 64 + ks * 16;
                    int kB = ks * 16;
                    unsigned ah[4];
                    int r = warp_m * 16 + tg;
                    ah[0] = *(const unsigned*)&Ah[r * 264 + kA + 2 * tiG];
                    ah[1] = *(const unsigned*)&Ah[(r + 8) * 264 + kA + 2 * tiG];
                    ah[2] = *(const unsigned*)&Ah[r * 264 + kA + 8 + 2 * tiG];
                    ah[3] = *(const unsigned*)&Ah[(r + 8) * 264 + kA + 8 + 2 * tiG];
#pragma unroll
                    for (int g = 0; g < 3; g++) {
                        int br = g * 64 + warp_n * 8 + tg;
                        unsigned b0 = *(const unsigned*)&Bh[br * 72 + kB + 2 * tiG];
                        unsigned b1 = *(const unsigned*)&Bh[br * 72 + kB + 8 + 2 * tiG];
                        mma16816(acc[g], ah, b0, b1);
                    }
                }
            }

            // gate math for this col chunk
            {
                float2 br2 = *(const float2*)&bh[ccol];
                float2 bz2 = *(const float2*)&bh[256 + ccol];
                float2 bn2 = *(const float2*)&bh[512 + ccol];
#pragma unroll
                for (int half = 0; half < 2; half++) {
                    int r = warp_m * 16 + tg + half * 8;
                    int ai = half * 2;
                    float rr0 = sigmoidf_(xr[half].x + acc[0][ai]     + br2.x);
                    float rr1 = sigmoidf_(xr[half].y + acc[0][ai + 1] + br2.y);
                    float zz0 = sigmoidf_(xz[half].x + acc[1][ai]     + bz2.x);
                    float zz1 = sigmoidf_(xz[half].y + acc[1][ai + 1] + bz2.y);
                    float nn0 = tanhf(xn[half].x + rr0 * (acc[2][ai]     + bn2.x));
                    float nn1 = tanhf(xn[half].y + rr1 * (acc[2][ai + 1] + bn2.y));
                    float2 hn;
                    hn.x = nn0 * (1.f - zz0) + ho[half].x * zz0;
                    hn.y = nn1 * (1.f - zz1) + ho[half].y * zz1;
                    *(float2*)&hsh[r * 258 + ccol] = hn;
                }
            }
        }
    }
    __syncthreads();
    for (int i = tid; i < 32 * HD; i += GRU_THREADS) {
        int r = i >> 8, c = i & 255;
        g_h[0][(size_t)(base + r) * HD + c] = hsh[r * 258 + c];
    }
}

// ---------------- final linear ----------------
__global__ void k_final(const float* __restrict__ linW, const float* __restrict__ linb,
                        const float* __restrict__ a1p, const float* __restrict__ a2p,
                        float* __restrict__ out) {
    __shared__ __align__(16) float As[64][33];
    __shared__ __align__(16) float Bs[32][64];
    float a1 = *a1p, a2 = *a2p;
    int tid = threadIdx.x;
    int rowbase = blockIdx.x * 64, cbase = blockIdx.y * 64;
    int tx = tid & 15, ty = tid >> 4;

    float acc[4][4];
#pragma unroll
    for (int j = 0; j < 4; j++)
#pragma unroll
        for (int u = 0; u < 4; u++) acc[j][u] = 0.f;

    for (int i0 = 0; i0 < HD; i0 += 32) {
        for (int t = tid; t < 64 * 32; t += 256) {
            int kk = t & 31, r = t >> 5;
            As[r][kk] = prelu_f(g_h[0][(size_t)(rowbase + r) * HD + i0 + kk], a1);
        }
        for (int t = tid; t < 32 * 64; t += 256) {
            int c = t & 63, kk = t >> 6;
            Bs[kk][c] = linW[(size_t)(i0 + kk) * HD + cbase + c];
        }
        __syncthreads();
#pragma unroll
        for (int kk = 0; kk < 32; kk++) {
            float a[4];
#pragma unroll
            for (int j = 0; j < 4; j++) a[j] = As[ty * 4 + j][kk];
            float4 b = *(const float4*)&Bs[kk][tx * 4];
#pragma unroll
            for (int j = 0; j < 4; j++) {
                acc[j][0] += a[j] * b.x; acc[j][1] += a[j] * b.y;
                acc[j][2] += a[j] * b.z; acc[j][3] += a[j] * b.w;
            }
        }
        __syncthreads();
    }
#pragma unroll
    for (int j = 0; j < 4; j++) {
        int row = rowbase + ty * 4 + j;
#pragma unroll
        for (int u = 0; u < 4; u++) {
            int c = cbase + tx * 4 + u;
            out[(size_t)row * 512 + 256 + c] = prelu_f(acc[j][u] + linb[c], a2);
        }
    }
}

// ---------------- launch ----------------
extern "C" void kernel_launch(void* const* d_in, const int* in_sizes, int n_in,
                              void* d_out, int out_size) {
    (void)in_sizes; (void)n_in; (void)out_size;
    const float* obs        = (const float*)d_in[0];
    const float* comm       = (const float*)d_in[1];
    const float* obs_emb    = (const float*)d_in[2];
    const float* obs_a_emb  = (const float*)d_in[3];
    const float* obs_W      = (const float*)d_in[4];
    const float* obs_b      = (const float*)d_in[5];
    const float* obs_a      = (const float*)d_in[6];
    const float* comm_emb   = (const float*)d_in[7];
    const float* comm_a_emb = (const float*)d_in[8];
    const float* cw1 = (const float*)d_in[9];
    const float* cb1 = (const float*)d_in[10];
    const float* cw3 = (const float*)d_in[11];
    const float* cb3 = (const float*)d_in[12];
    const float* cw5 = (const float*)d_in[13];
    const float* cb5 = (const float*)d_in[14];
    const float* cw7 = (const float*)d_in[15];
    const float* cb7 = (const float*)d_in[16];
    const float* bn_g  = (const float*)d_in[17];
    const float* bn_b  = (const float*)d_in[18];
    const float* cnn_a = (const float*)d_in[19];
    const float* Wx = (const float*)d_in[20];
    const float* bx = (const float*)d_in[21];
    const float* Wh = (const float*)d_in[22];
    const float* bh = (const float*)d_in[23];
    const float* lin_a1 = (const float*)d_in[24];
    const float* lin_W  = (const float*)d_in[25];
    const float* lin_b  = (const float*)d_in[26];
    const float* lin_a2 = (const float*)d_in[27];
    float* out = (float*)d_out;

    static int attr_set = 0;
    if (!attr_set) {
        cudaFuncSetAttribute(k_gru_mma, cudaFuncAttributeMaxDynamicSharedMemorySize, GRU_SMEM);
        attr_set = 1;
    }

    k_zero<<<1, 256>>>();
    k_obsM<<<dim3(16, 32), 256>>>(obs_emb, obs_a_emb, obs_W);
    k_Q<<<dim3(16, 8), 256>>>(comm_emb, comm_a_emb, cw1, cw3, cw5, cw7);
    k_tok<<<32768, 128>>>(comm);
    k_obsOut<<<4096, 256>>>(obs, obs_b, obs_a, out);
    k_ypre<<<4096, 256>>>(cb1, cb3, cb5, cb7);
    k_bnfin<<<1, 256>>>(bn_g, bn_b);
    k_Wcvt2<<<768, 256>>>(Wx, 0);
    k_Wcvt2<<<768, 256>>>(Wh, 1);
    k_xproj_mma<<<dim3(6, 1024), 256>>>(bx, cnn_a);
    k_gru_mma<<<128, GRU_THREADS, GRU_SMEM>>>(bh);
    k_final<<<dim3(64, 4), 256>>>(lin_W, lin_b, lin_a1, lin_a2, out);
}